// round 8
// baseline (speedup 1.0000x reference)
#include <cuda_runtime.h>
#include <math.h>

#define NB   128   // batch
#define NC   64    // channels
#define NH   64
#define NW   64
#define NPIX (NH*NW)
#define KK   49

typedef unsigned long long u64;

// ---- packed fp32x2 helpers (sm_100+ PTX; full IEEE fp32 per lane) ----------
__device__ __forceinline__ void fma2(u64& d, u64 a, u64 b) {
    asm("fma.rn.f32x2 %0, %1, %2, %0;" : "+l"(d) : "l"(a), "l"(b));
}
__device__ __forceinline__ float2 upk(u64 v) {
    float2 f; asm("mov.b64 {%0,%1}, %2;" : "=f"(f.x), "=f"(f.y) : "l"(v)); return f;
}

// ---------------- scratch (device globals; no allocations allowed) ----------
// Layout: [b][cb=0..3][pix][16ch]  (cb = 16-channel block)
__device__ __align__(16) float g_rubinw[NB*NPIX*NC];
__device__ __align__(16) float g_visn  [NB*NPIX*NC];
__device__ float g_costpart[NB*8*KK];
__device__ float g_poolr[NB*NH*NC];
__device__ float g_poolv[NB*NH*NC];
__device__ float g_Spart[NB*NH];

// =========================== Kernel A =======================================
// One block per (b, 2-row pair). 512 threads, 16 warps, TENSOR-SPECIALIZED:
// warps 0-7 -> rubin, 8-15 -> vis. Warp = (pixel-half ph, output-quarter ow):
// owns outputs ow*16..+15 for 64 pixels (2/thread). fma2 lanes pair ADJACENT
// CHANNELS: a = (x[c],x[c+1]) u64 straight from smem, b = (w[o][c],w[o][c+1])
// from natural [o][c] layout -> zero packing MOVs in the mainloop.
#define OFF_WR  0
#define OFF_WV  4352
#define OFF_XR  8704
#define OFF_XV  17408
#define OFF_SQR 26112
#define OFF_SQV 26624
#define OFF_PR  27136
#define OFF_PV  27648
#define OFF_GX  28160
#define OFF_FR  28224
#define OFF_SV  28352
#define OFF_SW  28480
#define KA_SMEM_FLOATS 28608

__global__ void __launch_bounds__(512, 1)
kA(const float* __restrict__ rubin, const float* __restrict__ vis,
   const float* __restrict__ wr, const float* __restrict__ wv, float inv_gsum)
{
    extern __shared__ float sm[];
    float* sWr = sm + OFF_WR;    // [o][c], stride 68
    float* sWv = sm + OFF_WV;
    float* sXr = sm + OFF_XR;    // [pix][c], 128 pixels, stride 68
    float* sXv = sm + OFF_XV;
    float* sSQR = sm + OFF_SQR;  // [4 ow][128 pix]
    float* sSQV = sm + OFF_SQV;
    float* sPr = sm + OFF_PR;    // [2rows][4q][64c]
    float* sPv = sm + OFF_PV;
    float* sGx = sm + OFF_GX;    // [64]
    float* sFr = sm + OFF_FR;    // [128]
    float* sSv = sm + OFF_SV;    // [128]
    float* sSw = sm + OFF_SW;    // [128]

    const int h0 = blockIdx.x * 2, b = blockIdx.y;
    const int tid = threadIdx.x;
    const int wid = tid >> 5, lane = tid & 31;
    const bool isR = (wid < 8);
    const int wq = wid & 7;
    const int ph = wq >> 2;          // pixel half: 0 or 1
    const int ow = wq & 3;           // output quarter
    const int og = ow * 16;

    // ---- weights -> smem natural [o][c] (coalesced in, contiguous out) ----
    for (int idx = tid; idx < 4096; idx += 512) {
        int o = idx >> 6, c = idx & 63;
        sWr[o*68 + c] = wr[idx];
        sWv[o*68 + c] = wv[idx];
    }
    if (tid < 64) {
        float xxg = -1.f + 2.f * (float)tid / 63.f;
        sGx[tid] = expf(-2.f * xxg * xxg);
    }

    // ---- stage x transposed: sX[pix][c], pix = r*64 + w ----
    {
        const int w0 = tid & 63;
        const int r  = (tid >> 6) & 1;
        const int cq = tid >> 7;               // 0..3
        const size_t rowbase = (size_t)b*NC*NPIX + (size_t)(h0 + r)*64 + w0;
        const int pofs = (r*64 + w0)*68;
#pragma unroll
        for (int it = 0; it < 4; it++) {
            int c0 = cq*4 + it*16;
            float4 vr, vv;
            vr.x = rubin[rowbase + (size_t)(c0+0)*NPIX];
            vr.y = rubin[rowbase + (size_t)(c0+1)*NPIX];
            vr.z = rubin[rowbase + (size_t)(c0+2)*NPIX];
            vr.w = rubin[rowbase + (size_t)(c0+3)*NPIX];
            vv.x = vis  [rowbase + (size_t)(c0+0)*NPIX];
            vv.y = vis  [rowbase + (size_t)(c0+1)*NPIX];
            vv.z = vis  [rowbase + (size_t)(c0+2)*NPIX];
            vv.w = vis  [rowbase + (size_t)(c0+3)*NPIX];
            *(float4*)&sXr[pofs + c0] = vr;
            *(float4*)&sXv[pofs + c0] = vv;
        }
    }
    __syncthreads();

    // ---- channel-pair f32x2 GEMM (no packing ops) ----
    const float* sX = isR ? sXr : sXv;
    const float* sW = isR ? sWr : sWv;
    const int p0 = ph*64 + lane, p1 = p0 + 32;

    u64 acc[2][16];    // [pixel][output]; lanes = even/odd channel partials
#pragma unroll
    for (int o = 0; o < 16; o++) { acc[0][o] = 0ull; acc[1][o] = 0ull; }

#pragma unroll 2
    for (int c0 = 0; c0 < 64; c0 += 4) {
        const ulonglong2 x0 = *(const ulonglong2*)&sX[p0*68 + c0];
        const ulonglong2 x1 = *(const ulonglong2*)&sX[p1*68 + c0];
#pragma unroll
        for (int o = 0; o < 16; o++) {
            const ulonglong2 w2 = *(const ulonglong2*)&sW[(og + o)*68 + c0];
            fma2(acc[0][o], x0.x, w2.x);
            fma2(acc[0][o], x0.y, w2.y);
            fma2(acc[1][o], x1.x, w2.x);
            fma2(acc[1][o], x1.y, w2.y);
        }
    }

    // horizontal add of even/odd partials
    float val[2][16];
#pragma unroll
    for (int p = 0; p < 2; p++)
#pragma unroll
        for (int o = 0; o < 16; o++) {
            float2 t = upk(acc[p][o]);
            val[p][o] = t.x + t.y;
        }

    // ---- pool partials over raw x (tid<256, identical to r7 mapping) ----
    if (tid < 256) {
        const int c = tid & 63, q = tid >> 6;
#pragma unroll
        for (int r = 0; r < 2; r++) {
            float pr = 0.f, pv = 0.f;
#pragma unroll
            for (int w = 0; w < 16; w++) {
                const int wcol = q*16 + w;
                const int px = r*64 + wcol;
                const float gxw = sGx[wcol];
                pr = fmaf(sXr[px*68 + c], gxw, pr);
                pv = fmaf(sXv[px*68 + c], gxw, pv);
            }
            sPr[(r*4 + q)*64 + c] = pr;
            sPv[(r*4 + q)*64 + c] = pv;
        }
    }

    // ---- per-(warp,pixel) square partials over this warp's 16 outputs ----
    {
        float* sSQ = isR ? sSQR : sSQV;
        float sq0 = 0.f, sq1 = 0.f;
#pragma unroll
        for (int o = 0; o < 16; o++) {
            sq0 = fmaf(val[0][o], val[0][o], sq0);
            sq1 = fmaf(val[1][o], val[1][o], sq1);
        }
        sSQ[ow*128 + p0] = sq0;
        sSQ[ow*128 + p1] = sq1;
    }
    __syncthreads();

    if (tid < 128) {
        const int pix = tid;           // r*64 + col
        const int r = pix >> 6, col = pix & 63;
        float ssr = 0.f, ssv = 0.f;
#pragma unroll
        for (int w = 0; w < 4; w++) { ssr += sSQR[w*128 + pix]; ssv += sSQV[w*128 + pix]; }
        const float sr = 1.f / fmaxf(sqrtf(ssr), 1e-6f);
        const float sv = 1.f / fmaxf(sqrtf(ssv), 1e-6f);
        const float e  = ssr * sr * sr;
        const float yy = -1.f + 2.f * (float)(h0 + r) / 63.f;
        const float gy = expf(-2.f*yy*yy);
        const float g  = gy * sGx[col] * inv_gsum;
        const float swraw = e * g;
        sFr[pix] = sr * swraw;
        sSv[pix] = sv;
        sSw[pix] = swraw;
        const float gyn = gy * inv_gsum;
        const int c = col;
        g_poolr[(b*NH + h0 + r)*NC + c] =
            (sPr[(r*4+0)*64+c] + sPr[(r*4+1)*64+c] + sPr[(r*4+2)*64+c] + sPr[(r*4+3)*64+c]) * gyn;
        g_poolv[(b*NH + h0 + r)*NC + c] =
            (sPv[(r*4+0)*64+c] + sPv[(r*4+1)*64+c] + sPv[(r*4+2)*64+c] + sPv[(r*4+3)*64+c]) * gyn;
    }
    __syncthreads();

    if (tid < 2) {
        float s = 0.f;
        for (int i = 0; i < 64; i++) s += sSw[tid*64 + i];
        g_Spart[b*NH + h0 + tid] = s;
    }

    // ---- scale and re-stage into own tensor's sX (raw x now dead) ----
    {
        float* sXo = isR ? sXr : sXv;
#pragma unroll
        for (int p = 0; p < 2; p++) {
            const int pix = (p == 0) ? p0 : p1;
            const float f = isR ? sFr[pix] : sSv[pix];
#pragma unroll
            for (int qq = 0; qq < 4; qq++) {
                float4 t;
                t.x = val[p][qq*4+0]*f; t.y = val[p][qq*4+1]*f;
                t.z = val[p][qq*4+2]*f; t.w = val[p][qq*4+3]*f;
                *(float4*)&sXo[pix*68 + og + qq*4] = t;
            }
        }
    }
    __syncthreads();

    // ---- coalesced global stores: layout [b][cb][pix][16] ----
    {
#pragma unroll
        for (int k = 0; k < 4; k++) {
            const int idx = k*512 + tid;      // f4 idx 0..2047
            const int q   = idx & 3;
            const int pix = (idx >> 2) & 127;
            const int cb  = idx >> 9;         // 0..3
            const size_t dst = ((size_t)(b*4 + cb)*NPIX + (size_t)h0*64 + pix)*16 + q*4;
            *(float4*)&g_rubinw[dst] = *(float4*)&sXr[pix*68 + cb*16 + q*4];
            *(float4*)&g_visn  [dst] = *(float4*)&sXv[pix*68 + cb*16 + q*4];
        }
    }
}

// =========================== Kernel B =======================================
// Correlation costs, channel-split threads. Block = (b, 8-row tile).
// 128 threads: q = tid&7 (channel pair -> one u64), cp = tid>>3 (4 cols).
// smem u64 layout: idx = t*640 + col*10 + q.
#define KB_SMEM_BYTES (14*640*8)   // 71680

__global__ void __launch_bounds__(128, 2)
kB()
{
    const int tile = blockIdx.x;            // 0..7
    const int b    = blockIdx.y;
    const int h0   = tile * 8;
    const int tid  = threadIdx.x;
    const int q    = tid & 7;               // channel pair (2q, 2q+1)
    const int cp   = tid >> 3;              // 0..15, cols 4cp..4cp+3

    extern __shared__ u64 sv64[];           // [t*640 + col*10 + q]

    u64 acc2[KK];
#pragma unroll
    for (int k = 0; k < KK; k++) acc2[k] = 0ull;

    for (int cb = 0; cb < 4; cb++) {
        const float* vplane = g_visn   + (size_t)(b*4 + cb)*NPIX*16;
        const float* rplane = g_rubinw + (size_t)(b*4 + cb)*NPIX*16;

        __syncthreads();
        for (int idx = tid; idx < 14*64*4; idx += 128) {
            const int m   = idx & 3;
            const int col = (idx >> 2) & 63;
            const int t   = idx >> 8;
            const int gr  = min(max(h0 + t - 3, 0), 63);
            *(float4*)&sv64[t*640 + col*10 + 2*m] =
                *(const float4*)(vplane + ((size_t)(gr*64 + col))*16 + m*4);
        }
        __syncthreads();

        u64 rb[8][4];
#pragma unroll
        for (int r = 0; r < 8; r++)
#pragma unroll
            for (int cc = 0; cc < 4; cc++)
                rb[r][cc] = *(const u64*)(rplane +
                    ((size_t)((h0 + r)*64 + 4*cp + cc))*16 + q*2);

#pragma unroll
        for (int t = 0; t < 14; t++) {
            u64 w[10];
#pragma unroll
            for (int j = 0; j < 10; j++) {
                const int colw = min(max(4*cp + j - 3, 0), 63);
                w[j] = sv64[t*640 + colw*10 + q];
            }
#pragma unroll
            for (int k = 0; k < 7; k++) {
                const int r = t - k;
                if (r >= 0 && r <= 7) {
#pragma unroll
                    for (int dx = 0; dx < 7; dx++) {
                        fma2(acc2[k*7 + dx], rb[r][0], w[dx]);
                        fma2(acc2[k*7 + dx], rb[r][1], w[dx+1]);
                        fma2(acc2[k*7 + dx], rb[r][2], w[dx+2]);
                        fma2(acc2[k*7 + dx], rb[r][3], w[dx+3]);
                    }
                }
            }
        }
    }

    __shared__ float sred[4][KK];
    const int wid = tid >> 5, lane = tid & 31;
#pragma unroll
    for (int k = 0; k < KK; k++) {
        float2 t = upk(acc2[k]);
        float v = t.x + t.y;
#pragma unroll
        for (int off = 16; off > 0; off >>= 1) v += __shfl_down_sync(0xffffffffu, v, off);
        if (lane == 0) sred[wid][k] = v;
    }
    __syncthreads();
    if (tid < KK)
        g_costpart[(b*8 + tile)*KK + tid] =
            sred[0][tid] + sred[1][tid] + sred[2][tid] + sred[3][tid];
}

// =========================== Kernel C =======================================
__device__ __forceinline__ float gelu_exact(float x) {
    return 0.5f * x * (1.f + erff(x * 0.70710678118654752440f));
}

__global__ void __launch_bounds__(128)
kC(const float* __restrict__ p2s, const int* __restrict__ band_idx,
   const float* __restrict__ log_temp, const float* __restrict__ band_emb,
   const float* __restrict__ w1, const float* __restrict__ b1,
   const float* __restrict__ w2, const float* __restrict__ b2,
   const float* __restrict__ w3, const float* __restrict__ b3,
   float* __restrict__ out, int stride)
{
    const int b = blockIdx.x, tid = threadIdx.x;
    __shared__ float sfeat[212];
    __shared__ float scost[KK];
    __shared__ float sh1[128], sh2[128], sout3[3];
    __shared__ float sS, scdx, scdy, sconf;

    if (tid == 0) {
        float s = 0.f;
        for (int h = 0; h < NH; h++) s += g_Spart[b*NH + h];
        sS = s;
    }
    if (tid < KK) {
        float c = 0.f;
        for (int t = 0; t < 8; t++) c += g_costpart[(b*8 + t)*KK + tid];
        scost[tid] = c;
    }
    if (tid < 64) {
        float pr = 0.f, pv = 0.f;
        for (int h = 0; h < NH; h++) {
            pr += g_poolr[(b*NH + h)*NC + tid];
            pv += g_poolv[(b*NH + h)*NC + tid];
        }
        sfeat[tid] = pr; sfeat[64 + tid] = pv; sfeat[128 + tid] = pr - pv;
    }
    __syncthreads();

    if (tid == 0) {
        const float temp  = fmaxf(expf(log_temp[0]), 1e-3f);
        const float scale = 1.f / ((sS + 1e-8f) * 8.f * temp);  // sqrt(C)=8
        float l[KK], mx = -1e30f;
        for (int k = 0; k < KK; k++) { l[k] = scost[k] * scale; mx = fmaxf(mx, l[k]); }
        float sum = 0.f;
        for (int k = 0; k < KK; k++) { float p = expf(l[k] - mx); l[k] = p; sum += p; }
        const float inv = 1.f / sum;
        float cdx = 0.f, cdy = 0.f, cf = 0.f;
        for (int k = 0; k < KK; k++) {
            float p = l[k] * inv;
            cf  = fmaxf(cf, p);
            cdx += p * (float)((k % 7) - 3);
            cdy += p * (float)((k / 7) - 3);
        }
        scdx = cdx; scdy = cdy; sconf = cf;
        sfeat[192] = cdx; sfeat[193] = cdy;
    }
    if (tid < 16) sfeat[194 + tid] = band_emb[band_idx[b]*16 + tid];
    __syncthreads();

    float a = b1[tid];
    for (int f = 0; f < 210; f++) a = fmaf(sfeat[f], w1[f*128 + tid], a);
    sh1[tid] = gelu_exact(a);
    __syncthreads();

    a = b2[tid];
    for (int f = 0; f < 128; f++) a = fmaf(sh1[f], w2[f*128 + tid], a);
    sh2[tid] = gelu_exact(a);
    __syncthreads();

    if (tid < 3) {
        float a3 = b3[tid];
        for (int f = 0; f < 128; f++) a3 = fmaf(sh2[f], w3[f*3 + tid], a3);
        sout3[tid] = a3;
    }
    __syncthreads();

    if (tid == 0) {
        const float dx = scdx + sout3[0];
        const float dy = scdy + sout3[1];
        const float ls = fminf(fmaxf(sout3[2], -6.f), 3.f);
        const float s0 = p2s[b*4 + 0]*dx + p2s[b*4 + 1]*dy;
        const float s1 = p2s[b*4 + 2]*dx + p2s[b*4 + 3]*dy;
        float* o = out + (size_t)b * stride;
        if (stride > 0) o[0] = dx;
        if (stride > 1) o[1] = dy;
        if (stride > 2) o[2] = s0;
        if (stride > 3) o[3] = s1;
        if (stride > 4) o[4] = ls;
        if (stride > 5) o[5] = sconf;
        for (int j = 6; j < stride; j++) o[j] = 0.f;
    }
}

// =========================== launch =========================================
extern "C" void kernel_launch(void* const* d_in, const int* in_sizes, int n_in,
                              void* d_out, int out_size)
{
    const float* rubin = (const float*)d_in[0];
    const float* vis   = (const float*)d_in[1];
    const float* p2s   = (const float*)d_in[2];
    const int*   bidx  = (const int*)  d_in[3];
    const float* wr    = (const float*)d_in[4];
    const float* wv    = (const float*)d_in[5];
    const float* lt    = (const float*)d_in[6];
    const float* bemb  = (const float*)d_in[7];
    const float* w1    = (const float*)d_in[8];
    const float* b1    = (const float*)d_in[9];
    const float* w2    = (const float*)d_in[10];
    const float* b2    = (const float*)d_in[11];
    const float* w3    = (const float*)d_in[12];
    const float* b3    = (const float*)d_in[13];
    float* out = (float*)d_out;
    const int stride = out_size / NB;

    // gauss normalizer (separable, H=W=64)
    double Sy = 0.0;
    for (int i = 0; i < 64; i++) {
        double y = -1.0 + 2.0 * (double)i / 63.0;
        Sy += exp(-2.0 * y * y);
    }
    const float inv_gsum = (float)(1.0 / (Sy * Sy));

    const int ka_smem = KA_SMEM_FLOATS * 4;   // 114432 B
    cudaFuncSetAttribute(kA, cudaFuncAttributeMaxDynamicSharedMemorySize, ka_smem);
    cudaFuncSetAttribute(kB, cudaFuncAttributeMaxDynamicSharedMemorySize, KB_SMEM_BYTES);

    kA<<<dim3(NH/2, NB), 512, ka_smem>>>(rubin, vis, wr, wv, inv_gsum);
    kB<<<dim3(8, NB), 128, KB_SMEM_BYTES>>>();
    kC<<<NB, 128>>>(p2s, bidx, lt, bemb, w1, b1, w2, b2, w3, b3, out, stride);
}

// round 9
// speedup vs baseline: 1.2596x; 1.2596x over previous
#include <cuda_runtime.h>
#include <math.h>

#define NB   128   // batch
#define NC   64    // channels
#define NH   64
#define NW   64
#define NPIX (NH*NW)
#define KK   49

typedef unsigned long long u64;

// ---- packed fp32x2 helpers (sm_100+ PTX; full IEEE fp32 per lane) ----------
__device__ __forceinline__ u64 splat2(float a) {
    u64 r; asm("mov.b64 %0, {%1,%1};" : "=l"(r) : "f"(a)); return r;
}
__device__ __forceinline__ void fma2(u64& d, u64 a, u64 b) {
    asm("fma.rn.f32x2 %0, %1, %2, %0;" : "+l"(d) : "l"(a), "l"(b));
}
__device__ __forceinline__ float2 upk(u64 v) {
    float2 f; asm("mov.b64 {%0,%1}, %2;" : "=f"(f.x), "=f"(f.y) : "l"(v)); return f;
}
#define GETC(v,cc) ((cc)==0?(v).x:(cc)==1?(v).y:(cc)==2?(v).z:(v).w)

// ---------------- scratch (device globals; no allocations allowed) ----------
// Layout: [b][cb=0..3][pix][16ch]  (cb = 16-channel block)
__device__ __align__(16) float g_rubinw[NB*NPIX*NC];
__device__ __align__(16) float g_visn  [NB*NPIX*NC];
__device__ float g_costpart[NB*8*KK];
__device__ float g_poolr[NB*NH*NC];
__device__ float g_poolv[NB*NH*NC];
__device__ float g_Spart[NB*NH];

// =========================== Kernel A (r7 version, reverted) ================
// One block per (b, 2-row pair). 256 threads, 8 warps, TENSOR-SPECIALIZED:
// warps 0-3 -> rubin, warps 4-7 -> vis. Each warp owns 16 outputs; each
// thread owns 4 pixels -> 32 u64 f32x2 accumulators.
#define OFF_WR  0
#define OFF_WV  4352
#define OFF_XR  8704
#define OFF_XV  17408
#define OFF_SQR 26112
#define OFF_SQV 26624
#define OFF_PR  27136
#define OFF_PV  27648
#define OFF_GX  28160
#define OFF_FR  28224
#define OFF_SV  28352
#define OFF_SW  28480
#define KA_SMEM_FLOATS 28608

__global__ void __launch_bounds__(256, 2)
kA(const float* __restrict__ rubin, const float* __restrict__ vis,
   const float* __restrict__ wr, const float* __restrict__ wv, float inv_gsum)
{
    extern __shared__ float sm[];
    float* sWr = sm + OFF_WR;    // [c][o], stride 68
    float* sWv = sm + OFF_WV;
    float* sXr = sm + OFF_XR;    // [pix][c], 128 pixels, stride 68
    float* sXv = sm + OFF_XV;
    float* sSQR = sm + OFF_SQR;  // [4][128]
    float* sSQV = sm + OFF_SQV;  // [4][128]
    float* sPr = sm + OFF_PR;    // [2rows][4q][64c]
    float* sPv = sm + OFF_PV;
    float* sGx = sm + OFF_GX;    // [64]
    float* sFr = sm + OFF_FR;    // [128]
    float* sSv = sm + OFF_SV;    // [128]
    float* sSw = sm + OFF_SW;    // [128]

    const int h0 = blockIdx.x * 2, b = blockIdx.y;
    const int tid = threadIdx.x;
    const int wid = tid >> 5, lane = tid & 31;
    const bool isR = (wid < 4);

    // ---- weights -> smem transposed [c][o] (coalesced global read) ----
    for (int idx = tid; idx < 4096; idx += 256) {
        int o = idx >> 6, c = idx & 63;
        sWr[c*68 + o] = wr[idx];
        sWv[c*68 + o] = wv[idx];
    }
    if (tid < 64) {
        float xxg = -1.f + 2.f * (float)tid / 63.f;
        sGx[tid] = expf(-2.f * xxg * xxg);
    }

    // ---- stage x transposed: sX[pix][c], pix = r*64 + w ----
    {
        const int w0 = tid & 63, cq = tid >> 6;
#pragma unroll
        for (int r = 0; r < 2; r++) {
            const size_t rowbase = (size_t)b*NC*NPIX + (size_t)(h0 + r)*64 + w0;
            const int pofs = (r*64 + w0)*68;
#pragma unroll
            for (int it = 0; it < 4; it++) {
                int c0 = cq*4 + it*16;
                float4 vr, vv;
                vr.x = rubin[rowbase + (size_t)(c0+0)*NPIX];
                vr.y = rubin[rowbase + (size_t)(c0+1)*NPIX];
                vr.z = rubin[rowbase + (size_t)(c0+2)*NPIX];
                vr.w = rubin[rowbase + (size_t)(c0+3)*NPIX];
                vv.x = vis  [rowbase + (size_t)(c0+0)*NPIX];
                vv.y = vis  [rowbase + (size_t)(c0+1)*NPIX];
                vv.z = vis  [rowbase + (size_t)(c0+2)*NPIX];
                vv.w = vis  [rowbase + (size_t)(c0+3)*NPIX];
                *(float4*)&sXr[pofs + c0] = vr;
                *(float4*)&sXv[pofs + c0] = vv;
            }
        }
    }
    __syncthreads();

    // ---- f32x2 register-tiled GEMM (one tensor per warp, 4 pixels/thread) --
    const int og = (wid & 3) * 16;
    const float* sX = isR ? sXr : sXv;
    const float* sW = isR ? sWr : sWv;

    u64 acc[4][8];     // [pixel][output-pair]
#pragma unroll
    for (int pp = 0; pp < 4; pp++)
#pragma unroll
        for (int j = 0; j < 8; j++) acc[pp][j] = 0ull;

#pragma unroll 2
    for (int c0 = 0; c0 < 64; c0 += 4) {
        float4 x[4];
#pragma unroll
        for (int pp = 0; pp < 4; pp++)
            x[pp] = *(const float4*)&sX[(lane + 32*pp)*68 + c0];
#pragma unroll
        for (int cc = 0; cc < 4; cc++) {
            const int c = c0 + cc;
            const ulonglong2 wa = *(const ulonglong2*)&sW[c*68 + og];
            const ulonglong2 wb = *(const ulonglong2*)&sW[c*68 + og + 4];
            const ulonglong2 wc = *(const ulonglong2*)&sW[c*68 + og + 8];
            const ulonglong2 wd = *(const ulonglong2*)&sW[c*68 + og + 12];
#pragma unroll
            for (int pp = 0; pp < 4; pp++) {
                const u64 s = splat2(GETC(x[pp], cc));
                fma2(acc[pp][0], wa.x, s); fma2(acc[pp][1], wa.y, s);
                fma2(acc[pp][2], wb.x, s); fma2(acc[pp][3], wb.y, s);
                fma2(acc[pp][4], wc.x, s); fma2(acc[pp][5], wc.y, s);
                fma2(acc[pp][6], wd.x, s); fma2(acc[pp][7], wd.y, s);
            }
        }
    }

    // ---- pool partials over raw x (still resident in sXr/sXv) ----
    {
        const int c = tid & 63, q = tid >> 6;
#pragma unroll
        for (int r = 0; r < 2; r++) {
            float pr = 0.f, pv = 0.f;
#pragma unroll
            for (int w = 0; w < 16; w++) {
                const int wcol = q*16 + w;
                const int px = r*64 + wcol;
                const float gxw = sGx[wcol];
                pr = fmaf(sXr[px*68 + c], gxw, pr);
                pv = fmaf(sXv[px*68 + c], gxw, pv);
            }
            sPr[(r*4 + q)*64 + c] = pr;
            sPv[(r*4 + q)*64 + c] = pv;
        }
    }

    // ---- per-(warp,pixel) square partials over this warp's 16 outputs ----
    {
        float* sSQ = isR ? sSQR : sSQV;
#pragma unroll
        for (int pp = 0; pp < 4; pp++) {
            float sq = 0.f;
#pragma unroll
            for (int j = 0; j < 8; j++) {
                float2 t = upk(acc[pp][j]);
                sq = fmaf(t.x, t.x, fmaf(t.y, t.y, sq));
            }
            sSQ[(wid & 3)*128 + lane + 32*pp] = sq;
        }
    }
    __syncthreads();

    if (tid < 128) {
        const int pix = tid;           // r*64 + col
        const int r = pix >> 6, col = pix & 63;
        float ssr = 0.f, ssv = 0.f;
#pragma unroll
        for (int w = 0; w < 4; w++) { ssr += sSQR[w*128 + pix]; ssv += sSQV[w*128 + pix]; }
        const float sr = 1.f / fmaxf(sqrtf(ssr), 1e-6f);
        const float sv = 1.f / fmaxf(sqrtf(ssv), 1e-6f);
        const float e  = ssr * sr * sr;
        const float yy = -1.f + 2.f * (float)(h0 + r) / 63.f;
        const float gy = expf(-2.f*yy*yy);
        const float g  = gy * sGx[col] * inv_gsum;
        const float swraw = e * g;
        sFr[pix] = sr * swraw;
        sSv[pix] = sv;
        sSw[pix] = swraw;
        const float gyn = gy * inv_gsum;
        const int c = col;
        g_poolr[(b*NH + h0 + r)*NC + c] =
            (sPr[(r*4+0)*64+c] + sPr[(r*4+1)*64+c] + sPr[(r*4+2)*64+c] + sPr[(r*4+3)*64+c]) * gyn;
        g_poolv[(b*NH + h0 + r)*NC + c] =
            (sPv[(r*4+0)*64+c] + sPv[(r*4+1)*64+c] + sPv[(r*4+2)*64+c] + sPv[(r*4+3)*64+c]) * gyn;
    }
    __syncthreads();

    if (tid < 2) {
        float s = 0.f;
        for (int i = 0; i < 64; i++) s += sSw[tid*64 + i];
        g_Spart[b*NH + h0 + tid] = s;
    }

    // ---- scale accums and re-stage into own tensor's sX (raw x now dead) ----
    {
        float* sXo = isR ? sXr : sXv;
#pragma unroll
        for (int pp = 0; pp < 4; pp++) {
            const int pix = lane + 32*pp;
            const float f = isR ? sFr[pix] : sSv[pix];
#pragma unroll
            for (int q = 0; q < 4; q++) {
                float2 ta = upk(acc[pp][2*q]), tb = upk(acc[pp][2*q+1]);
                float4 t; t.x = ta.x*f; t.y = ta.y*f; t.z = tb.x*f; t.w = tb.y*f;
                *(float4*)&sXo[pix*68 + og + 4*q] = t;
            }
        }
    }
    __syncthreads();

    // ---- coalesced global stores: layout [b][cb][pix][16] ----
    {
#pragma unroll
        for (int k = 0; k < 8; k++) {
            const int idx = k*256 + tid;      // f4 idx 0..2047
            const int q   = idx & 3;
            const int pix = (idx >> 2) & 127;
            const int cb  = idx >> 9;         // 0..3
            const size_t dst = ((size_t)(b*4 + cb)*NPIX + (size_t)h0*64 + pix)*16 + q*4;
            *(float4*)&g_rubinw[dst] = *(float4*)&sXr[pix*68 + cb*16 + q*4];
            *(float4*)&g_visn  [dst] = *(float4*)&sXv[pix*68 + cb*16 + q*4];
        }
    }
}

// =========================== Kernel B =======================================
// Correlation costs, 8-channel chunks for occupancy 3 (12 warps/SM).
// Block = (b, 8-row tile). 128 threads: q = tid&3 (channel pair within the
// 8-ch chunk), cp = tid>>2 (2 cols: 2cp, 2cp+1). Each thread covers all 8
// rows. smem u64 layout: idx = t*384 + col*6 + q -> per 16-lane phase the
// varying index is 12cp+q, distinct mod 16 -> conflict-free LDS.64.
#define KB_SMEM_BYTES (14*384*8)   // 43008

__global__ void __launch_bounds__(128, 3)
kB()
{
    const int tile = blockIdx.x;            // 0..7
    const int b    = blockIdx.y;
    const int h0   = tile * 8;
    const int tid  = threadIdx.x;
    const int q    = tid & 3;               // channel pair (2q, 2q+1) of chunk
    const int cp   = tid >> 2;              // 0..31, cols 2cp, 2cp+1

    extern __shared__ u64 sv64[];           // [t*384 + col*6 + q]

    u64 acc2[KK];
#pragma unroll
    for (int k = 0; k < KK; k++) acc2[k] = 0ull;

    for (int ch = 0; ch < 8; ch++) {        // 8-channel chunks
        const int cb = ch >> 1, half = ch & 1;
        const float* vplane = g_visn   + (size_t)(b*4 + cb)*NPIX*16 + half*8;
        const float* rplane = g_rubinw + (size_t)(b*4 + cb)*NPIX*16 + half*8;

        __syncthreads();
        // stage 14 window rows x 64 cols x 8 ch (2 f4 per col)
        for (int idx = tid; idx < 14*64*2; idx += 128) {
            const int m   = idx & 1;
            const int col = (idx >> 1) & 63;
            const int t   = idx >> 7;
            const int gr  = min(max(h0 + t - 3, 0), 63);
            *(float4*)&sv64[t*384 + col*6 + 2*m] =
                *(const float4*)(vplane + ((size_t)(gr*64 + col))*16 + m*4);
        }
        __syncthreads();

        // rubin registers: 8 rows x 2 cols x 2 ch (one u64 each)
        u64 rb[8][2];
#pragma unroll
        for (int r = 0; r < 8; r++)
#pragma unroll
            for (int cc = 0; cc < 2; cc++)
                rb[r][cc] = *(const u64*)(rplane +
                    ((size_t)((h0 + r)*64 + 2*cp + cc))*16 + q*2);

        // window loop: t = local window row (global h0 + t - 3)
#pragma unroll
        for (int t = 0; t < 14; t++) {
            u64 w[8];
#pragma unroll
            for (int j = 0; j < 8; j++) {
                const int colw = min(max(2*cp + j - 3, 0), 63);
                w[j] = sv64[t*384 + colw*6 + q];
            }
#pragma unroll
            for (int k = 0; k < 7; k++) {
                const int r = t - k;
                if (r >= 0 && r <= 7) {
#pragma unroll
                    for (int dx = 0; dx < 7; dx++) {
                        fma2(acc2[k*7 + dx], rb[r][0], w[dx]);
                        fma2(acc2[k*7 + dx], rb[r][1], w[dx+1]);
                    }
                }
            }
        }
    }

    __shared__ float sred[4][KK];
    const int wid = tid >> 5, lane = tid & 31;
#pragma unroll
    for (int k = 0; k < KK; k++) {
        float2 t = upk(acc2[k]);
        float v = t.x + t.y;
#pragma unroll
        for (int off = 16; off > 0; off >>= 1) v += __shfl_down_sync(0xffffffffu, v, off);
        if (lane == 0) sred[wid][k] = v;
    }
    __syncthreads();
    if (tid < KK)
        g_costpart[(b*8 + tile)*KK + tid] =
            sred[0][tid] + sred[1][tid] + sred[2][tid] + sred[3][tid];
}

// =========================== Kernel C =======================================
__device__ __forceinline__ float gelu_exact(float x) {
    return 0.5f * x * (1.f + erff(x * 0.70710678118654752440f));
}

__global__ void __launch_bounds__(128)
kC(const float* __restrict__ p2s, const int* __restrict__ band_idx,
   const float* __restrict__ log_temp, const float* __restrict__ band_emb,
   const float* __restrict__ w1, const float* __restrict__ b1,
   const float* __restrict__ w2, const float* __restrict__ b2,
   const float* __restrict__ w3, const float* __restrict__ b3,
   float* __restrict__ out, int stride)
{
    const int b = blockIdx.x, tid = threadIdx.x;
    __shared__ float sfeat[212];
    __shared__ float scost[KK];
    __shared__ float sh1[128], sh2[128], sout3[3];
    __shared__ float sS, scdx, scdy, sconf;

    if (tid == 0) {
        float s = 0.f;
        for (int h = 0; h < NH; h++) s += g_Spart[b*NH + h];
        sS = s;
    }
    if (tid < KK) {
        float c = 0.f;
        for (int t = 0; t < 8; t++) c += g_costpart[(b*8 + t)*KK + tid];
        scost[tid] = c;
    }
    if (tid < 64) {
        float pr = 0.f, pv = 0.f;
        for (int h = 0; h < NH; h++) {
            pr += g_poolr[(b*NH + h)*NC + tid];
            pv += g_poolv[(b*NH + h)*NC + tid];
        }
        sfeat[tid] = pr; sfeat[64 + tid] = pv; sfeat[128 + tid] = pr - pv;
    }
    __syncthreads();

    if (tid == 0) {
        const float temp  = fmaxf(expf(log_temp[0]), 1e-3f);
        const float scale = 1.f / ((sS + 1e-8f) * 8.f * temp);  // sqrt(C)=8
        float l[KK], mx = -1e30f;
        for (int k = 0; k < KK; k++) { l[k] = scost[k] * scale; mx = fmaxf(mx, l[k]); }
        float sum = 0.f;
        for (int k = 0; k < KK; k++) { float p = expf(l[k] - mx); l[k] = p; sum += p; }
        const float inv = 1.f / sum;
        float cdx = 0.f, cdy = 0.f, cf = 0.f;
        for (int k = 0; k < KK; k++) {
            float p = l[k] * inv;
            cf  = fmaxf(cf, p);
            cdx += p * (float)((k % 7) - 3);
            cdy += p * (float)((k / 7) - 3);
        }
        scdx = cdx; scdy = cdy; sconf = cf;
        sfeat[192] = cdx; sfeat[193] = cdy;
    }
    if (tid < 16) sfeat[194 + tid] = band_emb[band_idx[b]*16 + tid];
    __syncthreads();

    float a = b1[tid];
    for (int f = 0; f < 210; f++) a = fmaf(sfeat[f], w1[f*128 + tid], a);
    sh1[tid] = gelu_exact(a);
    __syncthreads();

    a = b2[tid];
    for (int f = 0; f < 128; f++) a = fmaf(sh1[f], w2[f*128 + tid], a);
    sh2[tid] = gelu_exact(a);
    __syncthreads();

    if (tid < 3) {
        float a3 = b3[tid];
        for (int f = 0; f < 128; f++) a3 = fmaf(sh2[f], w3[f*3 + tid], a3);
        sout3[tid] = a3;
    }
    __syncthreads();

    if (tid == 0) {
        const float dx = scdx + sout3[0];
        const float dy = scdy + sout3[1];
        const float ls = fminf(fmaxf(sout3[2], -6.f), 3.f);
        const float s0 = p2s[b*4 + 0]*dx + p2s[b*4 + 1]*dy;
        const float s1 = p2s[b*4 + 2]*dx + p2s[b*4 + 3]*dy;
        float* o = out + (size_t)b * stride;
        if (stride > 0) o[0] = dx;
        if (stride > 1) o[1] = dy;
        if (stride > 2) o[2] = s0;
        if (stride > 3) o[3] = s1;
        if (stride > 4) o[4] = ls;
        if (stride > 5) o[5] = sconf;
        for (int j = 6; j < stride; j++) o[j] = 0.f;
    }
}

// =========================== launch =========================================
extern "C" void kernel_launch(void* const* d_in, const int* in_sizes, int n_in,
                              void* d_out, int out_size)
{
    const float* rubin = (const float*)d_in[0];
    const float* vis   = (const float*)d_in[1];
    const float* p2s   = (const float*)d_in[2];
    const int*   bidx  = (const int*)  d_in[3];
    const float* wr    = (const float*)d_in[4];
    const float* wv    = (const float*)d_in[5];
    const float* lt    = (const float*)d_in[6];
    const float* bemb  = (const float*)d_in[7];
    const float* w1    = (const float*)d_in[8];
    const float* b1    = (const float*)d_in[9];
    const float* w2    = (const float*)d_in[10];
    const float* b2    = (const float*)d_in[11];
    const float* w3    = (const float*)d_in[12];
    const float* b3    = (const float*)d_in[13];
    float* out = (float*)d_out;
    const int stride = out_size / NB;

    // gauss normalizer (separable, H=W=64)
    double Sy = 0.0;
    for (int i = 0; i < 64; i++) {
        double y = -1.0 + 2.0 * (double)i / 63.0;
        Sy += exp(-2.0 * y * y);
    }
    const float inv_gsum = (float)(1.0 / (Sy * Sy));

    const int ka_smem = KA_SMEM_FLOATS * 4;   // 114432 B
    cudaFuncSetAttribute(kA, cudaFuncAttributeMaxDynamicSharedMemorySize, ka_smem);
    cudaFuncSetAttribute(kB, cudaFuncAttributeMaxDynamicSharedMemorySize, KB_SMEM_BYTES);

    kA<<<dim3(NH/2, NB), 256, ka_smem>>>(rubin, vis, wr, wv, inv_gsum);
    kB<<<dim3(8, NB), 128, KB_SMEM_BYTES>>>();
    kC<<<NB, 128>>>(p2s, bidx, lt, bemb, w1, b1, w2, b2, w3, b3, out, stride);
}

// round 12
// speedup vs baseline: 1.2699x; 1.0082x over previous
#include <cuda_runtime.h>
#include <math.h>

#define NB   128   // batch
#define NC   64    // channels
#define NH   64
#define NW   64
#define NPIX (NH*NW)
#define KK   49

typedef unsigned long long u64;

// ---- packed fp32x2 helpers (sm_100+ PTX; full IEEE fp32 per lane) ----------
__device__ __forceinline__ u64 splat2(float a) {
    u64 r; asm("mov.b64 %0, {%1,%1};" : "=l"(r) : "f"(a)); return r;
}
__device__ __forceinline__ void fma2(u64& d, u64 a, u64 b) {
    asm("fma.rn.f32x2 %0, %1, %2, %0;" : "+l"(d) : "l"(a), "l"(b));
}
__device__ __forceinline__ float2 upk(u64 v) {
    float2 f; asm("mov.b64 {%0,%1}, %2;" : "=f"(f.x), "=f"(f.y) : "l"(v)); return f;
}
#define GETC(v,cc) ((cc)==0?(v).x:(cc)==1?(v).y:(cc)==2?(v).z:(v).w)

// ---------------- scratch (device globals; no allocations allowed) ----------
// FLAT layout: [b][pix][64ch]
__device__ __align__(16) float g_rubinw[NB*NPIX*NC];
__device__ __align__(16) float g_visn  [NB*NPIX*NC];
__device__ float g_costpart[NB*8*KK];
__device__ float g_poolr[NB*NH*NC];
__device__ float g_poolv[NB*NH*NC];
__device__ float g_Spart[NB*NH];

// =========================== Kernel A (r5 version) ==========================
// One block per (b, 2-row pair). 256 threads, 8 warps, TENSOR-SPECIALIZED:
// warps 0-3 -> rubin, warps 4-7 -> vis. Each warp owns 16 outputs; each
// thread owns 4 pixels -> 32 u64 f32x2 accumulators.
#define OFF_WR  0
#define OFF_WV  4352
#define OFF_XR  8704
#define OFF_XV  17408
#define OFF_SQR 26112
#define OFF_SQV 26624
#define OFF_PR  27136
#define OFF_PV  27648
#define OFF_GX  28160
#define OFF_FR  28224
#define OFF_SV  28352
#define OFF_SW  28480
#define KA_SMEM_FLOATS 28608

__global__ void __launch_bounds__(256, 2)
kA(const float* __restrict__ rubin, const float* __restrict__ vis,
   const float* __restrict__ wr, const float* __restrict__ wv, float inv_gsum)
{
    extern __shared__ float sm[];
    float* sWr = sm + OFF_WR;    // [c][o], stride 68
    float* sWv = sm + OFF_WV;
    float* sXr = sm + OFF_XR;    // [pix][c], 128 pixels, stride 68
    float* sXv = sm + OFF_XV;
    float* sSQR = sm + OFF_SQR;  // [4][128]
    float* sSQV = sm + OFF_SQV;  // [4][128]
    float* sPr = sm + OFF_PR;    // [2rows][4q][64c]
    float* sPv = sm + OFF_PV;
    float* sGx = sm + OFF_GX;    // [64]
    float* sFr = sm + OFF_FR;    // [128]
    float* sSv = sm + OFF_SV;    // [128]
    float* sSw = sm + OFF_SW;    // [128]

    const int h0 = blockIdx.x * 2, b = blockIdx.y;
    const int tid = threadIdx.x;
    const int wid = tid >> 5, lane = tid & 31;
    const bool isR = (wid < 4);

    // ---- weights -> smem transposed [c][o] (coalesced global read) ----
    for (int idx = tid; idx < 4096; idx += 256) {
        int o = idx >> 6, c = idx & 63;
        sWr[c*68 + o] = wr[idx];
        sWv[c*68 + o] = wv[idx];
    }
    if (tid < 64) {
        float xxg = -1.f + 2.f * (float)tid / 63.f;
        sGx[tid] = expf(-2.f * xxg * xxg);
    }

    // ---- stage x transposed: sX[pix][c], pix = r*64 + w ----
    {
        const int w0 = tid & 63, cq = tid >> 6;
#pragma unroll
        for (int r = 0; r < 2; r++) {
            const size_t rowbase = (size_t)b*NC*NPIX + (size_t)(h0 + r)*64 + w0;
            const int pofs = (r*64 + w0)*68;
#pragma unroll
            for (int it = 0; it < 4; it++) {
                int c0 = cq*4 + it*16;
                float4 vr, vv;
                vr.x = rubin[rowbase + (size_t)(c0+0)*NPIX];
                vr.y = rubin[rowbase + (size_t)(c0+1)*NPIX];
                vr.z = rubin[rowbase + (size_t)(c0+2)*NPIX];
                vr.w = rubin[rowbase + (size_t)(c0+3)*NPIX];
                vv.x = vis  [rowbase + (size_t)(c0+0)*NPIX];
                vv.y = vis  [rowbase + (size_t)(c0+1)*NPIX];
                vv.z = vis  [rowbase + (size_t)(c0+2)*NPIX];
                vv.w = vis  [rowbase + (size_t)(c0+3)*NPIX];
                *(float4*)&sXr[pofs + c0] = vr;
                *(float4*)&sXv[pofs + c0] = vv;
            }
        }
    }
    __syncthreads();

    // ---- f32x2 register-tiled GEMM (one tensor per warp, 4 pixels/thread) --
    const int og = (wid & 3) * 16;
    const float* sX = isR ? sXr : sXv;
    const float* sW = isR ? sWr : sWv;

    u64 acc[4][8];     // [pixel][output-pair]
#pragma unroll
    for (int pp = 0; pp < 4; pp++)
#pragma unroll
        for (int j = 0; j < 8; j++) acc[pp][j] = 0ull;

#pragma unroll 2
    for (int c0 = 0; c0 < 64; c0 += 4) {
        float4 x[4];
#pragma unroll
        for (int pp = 0; pp < 4; pp++)
            x[pp] = *(const float4*)&sX[(lane + 32*pp)*68 + c0];
#pragma unroll
        for (int cc = 0; cc < 4; cc++) {
            const int c = c0 + cc;
            const ulonglong2 wa = *(const ulonglong2*)&sW[c*68 + og];
            const ulonglong2 wb = *(const ulonglong2*)&sW[c*68 + og + 4];
            const ulonglong2 wc = *(const ulonglong2*)&sW[c*68 + og + 8];
            const ulonglong2 wd = *(const ulonglong2*)&sW[c*68 + og + 12];
#pragma unroll
            for (int pp = 0; pp < 4; pp++) {
                const u64 s = splat2(GETC(x[pp], cc));
                fma2(acc[pp][0], wa.x, s); fma2(acc[pp][1], wa.y, s);
                fma2(acc[pp][2], wb.x, s); fma2(acc[pp][3], wb.y, s);
                fma2(acc[pp][4], wc.x, s); fma2(acc[pp][5], wc.y, s);
                fma2(acc[pp][6], wd.x, s); fma2(acc[pp][7], wd.y, s);
            }
        }
    }

    // ---- pool partials over raw x (still resident in sXr/sXv) ----
    {
        const int c = tid & 63, q = tid >> 6;
#pragma unroll
        for (int r = 0; r < 2; r++) {
            float pr = 0.f, pv = 0.f;
#pragma unroll
            for (int w = 0; w < 16; w++) {
                const int wcol = q*16 + w;
                const int px = r*64 + wcol;
                const float gxw = sGx[wcol];
                pr = fmaf(sXr[px*68 + c], gxw, pr);
                pv = fmaf(sXv[px*68 + c], gxw, pv);
            }
            sPr[(r*4 + q)*64 + c] = pr;
            sPv[(r*4 + q)*64 + c] = pv;
        }
    }

    // ---- per-(warp,pixel) square partials over this warp's 16 outputs ----
    {
        float* sSQ = isR ? sSQR : sSQV;
#pragma unroll
        for (int pp = 0; pp < 4; pp++) {
            float sq = 0.f;
#pragma unroll
            for (int j = 0; j < 8; j++) {
                float2 t = upk(acc[pp][j]);
                sq = fmaf(t.x, t.x, fmaf(t.y, t.y, sq));
            }
            sSQ[(wid & 3)*128 + lane + 32*pp] = sq;
        }
    }
    __syncthreads();

    if (tid < 128) {
        const int pix = tid;           // r*64 + col
        const int r = pix >> 6, col = pix & 63;
        float ssr = 0.f, ssv = 0.f;
#pragma unroll
        for (int w = 0; w < 4; w++) { ssr += sSQR[w*128 + pix]; ssv += sSQV[w*128 + pix]; }
        const float sr = 1.f / fmaxf(sqrtf(ssr), 1e-6f);
        const float sv = 1.f / fmaxf(sqrtf(ssv), 1e-6f);
        const float e  = ssr * sr * sr;
        const float yy = -1.f + 2.f * (float)(h0 + r) / 63.f;
        const float gy = expf(-2.f*yy*yy);
        const float g  = gy * sGx[col] * inv_gsum;
        const float swraw = e * g;
        sFr[pix] = sr * swraw;
        sSv[pix] = sv;
        sSw[pix] = swraw;
        const float gyn = gy * inv_gsum;
        const int c = col;
        g_poolr[(b*NH + h0 + r)*NC + c] =
            (sPr[(r*4+0)*64+c] + sPr[(r*4+1)*64+c] + sPr[(r*4+2)*64+c] + sPr[(r*4+3)*64+c]) * gyn;
        g_poolv[(b*NH + h0 + r)*NC + c] =
            (sPv[(r*4+0)*64+c] + sPv[(r*4+1)*64+c] + sPv[(r*4+2)*64+c] + sPv[(r*4+3)*64+c]) * gyn;
    }
    __syncthreads();

    if (tid < 2) {
        float s = 0.f;
        for (int i = 0; i < 64; i++) s += sSw[tid*64 + i];
        g_Spart[b*NH + h0 + tid] = s;
    }

    // ---- scale accums and re-stage into own tensor's sX (raw x now dead) ----
    {
        float* sXo = isR ? sXr : sXv;
#pragma unroll
        for (int pp = 0; pp < 4; pp++) {
            const int pix = lane + 32*pp;
            const float f = isR ? sFr[pix] : sSv[pix];
#pragma unroll
            for (int q = 0; q < 4; q++) {
                float2 ta = upk(acc[pp][2*q]), tb = upk(acc[pp][2*q+1]);
                float4 t; t.x = ta.x*f; t.y = ta.y*f; t.z = tb.x*f; t.w = tb.y*f;
                *(float4*)&sXo[pix*68 + og + 4*q] = t;
            }
        }
    }
    __syncthreads();

    // ---- coalesced global stores: FLAT layout [b][pix][64] ----
    {
        const size_t gbase = ((size_t)(b*NPIX + h0*64)) * NC;
#pragma unroll
        for (int k = 0; k < 8; k++) {
            const int idx = k*256 + tid;      // f4 idx 0..2047
            const int pix = idx >> 4;
            const int c4  = (idx & 15) * 4;
            *(float4*)&g_rubinw[gbase + pix*64 + c4] = *(float4*)&sXr[pix*68 + c4];
            *(float4*)&g_visn  [gbase + pix*64 + c4] = *(float4*)&sXv[pix*68 + c4];
        }
    }
}

// =========================== Kernel B =======================================
// Correlation costs, 8-channel chunks, cp.async DOUBLE-BUFFERED staging.
// Block = (b, 8-row tile), 128 threads: q = tid&3 (channel pair of chunk),
// cp = tid>>2 (cols 2cp, 2cp+1). smem u64 idx = t*384 + col*6 + q
// (conflict-free). 2 buffers x 43008 B -> occupancy 2, staging overlapped.
#define KB_CHUNK_U64 (14*384)
#define KB_SMEM_BYTES (2*KB_CHUNK_U64*8)   // 86016

__global__ void __launch_bounds__(128, 2)
kB()
{
    const int tile = blockIdx.x;            // 0..7
    const int b    = blockIdx.y;
    const int h0   = tile * 8;
    const int tid  = threadIdx.x;
    const int q    = tid & 3;               // channel pair (2q, 2q+1) of chunk
    const int cp   = tid >> 2;              // 0..31, cols 2cp, 2cp+1

    extern __shared__ u64 sbuf[];           // [2][KB_CHUNK_U64]

    const float* vbat = g_visn   + (size_t)b*NPIX*64;
    const float* rbat = g_rubinw + (size_t)b*NPIX*64;

    auto stage = [&](int ch, int bufi) {
        u64* dst = sbuf + bufi*KB_CHUNK_U64;
        const float* vpl = vbat + ch*8;
        for (int idx = tid; idx < 14*64*2; idx += 128) {
            const int m   = idx & 1;
            const int col = (idx >> 1) & 63;
            const int t   = idx >> 7;
            const int gr  = min(max(h0 + t - 3, 0), 63);
            const float* src = vpl + ((size_t)(gr*64 + col))*64 + m*4;
            unsigned d = (unsigned)__cvta_generic_to_shared(&dst[t*384 + col*6 + 2*m]);
            asm volatile("cp.async.cg.shared.global [%0], [%1], 16;"
                         :: "r"(d), "l"(src) : "memory");
        }
        asm volatile("cp.async.commit_group;" ::: "memory");
    };

    u64 acc2[KK];
#pragma unroll
    for (int k = 0; k < KK; k++) acc2[k] = 0ull;

    stage(0, 0);

    for (int ch = 0; ch < 8; ch++) {        // 8-channel chunks
        // rb loads (independent of smem) - issue before the wait
        u64 rb[8][2];
        const float* rpl = rbat + ch*8 + q*2;
#pragma unroll
        for (int r = 0; r < 8; r++)
#pragma unroll
            for (int cc = 0; cc < 2; cc++)
                rb[r][cc] = *(const u64*)(rpl + ((size_t)((h0 + r)*64 + 2*cp + cc))*64);

        asm volatile("cp.async.wait_group 0;" ::: "memory");
        __syncthreads();
        if (ch < 7) stage(ch + 1, (ch + 1) & 1);

        const u64* sv64 = sbuf + (ch & 1)*KB_CHUNK_U64;

#pragma unroll
        for (int t = 0; t < 14; t++) {
            u64 w[8];
#pragma unroll
            for (int j = 0; j < 8; j++) {
                const int colw = min(max(2*cp + j - 3, 0), 63);
                w[j] = sv64[t*384 + colw*6 + q];
            }
#pragma unroll
            for (int k = 0; k < 7; k++) {
                const int r = t - k;
                if (r >= 0 && r <= 7) {
#pragma unroll
                    for (int dx = 0; dx < 7; dx++) {
                        fma2(acc2[k*7 + dx], rb[r][0], w[dx]);
                        fma2(acc2[k*7 + dx], rb[r][1], w[dx+1]);
                    }
                }
            }
        }
    }

    __shared__ float sred[4][KK];
    const int wid = tid >> 5, lane = tid & 31;
#pragma unroll
    for (int k = 0; k < KK; k++) {
        float2 t = upk(acc2[k]);
        float v = t.x + t.y;
#pragma unroll
        for (int off = 16; off > 0; off >>= 1) v += __shfl_down_sync(0xffffffffu, v, off);
        if (lane == 0) sred[wid][k] = v;
    }
    __syncthreads();
    if (tid < KK)
        g_costpart[(b*8 + tile)*KK + tid] =
            sred[0][tid] + sred[1][tid] + sred[2][tid] + sred[3][tid];
}

// =========================== Kernel C =======================================
__device__ __forceinline__ float gelu_exact(float x) {
    return 0.5f * x * (1.f + erff(x * 0.70710678118654752440f));
}

__global__ void __launch_bounds__(128)
kC(const float* __restrict__ p2s, const int* __restrict__ band_idx,
   const float* __restrict__ log_temp, const float* __restrict__ band_emb,
   const float* __restrict__ w1, const float* __restrict__ b1,
   const float* __restrict__ w2, const float* __restrict__ b2,
   const float* __restrict__ w3, const float* __restrict__ b3,
   float* __restrict__ out, int stride)
{
    const int b = blockIdx.x, tid = threadIdx.x;
    __shared__ float sfeat[212];
    __shared__ float scost[KK];
    __shared__ float sh1[128], sh2[128], sout3[3];
    __shared__ float sS, scdx, scdy, sconf;

    if (tid == 0) {
        float s = 0.f;
        for (int h = 0; h < NH; h++) s += g_Spart[b*NH + h];
        sS = s;
    }
    if (tid < KK) {
        float c = 0.f;
        for (int t = 0; t < 8; t++) c += g_costpart[(b*8 + t)*KK + tid];
        scost[tid] = c;
    }
    if (tid < 64) {
        float pr = 0.f, pv = 0.f;
        for (int h = 0; h < NH; h++) {
            pr += g_poolr[(b*NH + h)*NC + tid];
            pv += g_poolv[(b*NH + h)*NC + tid];
        }
        sfeat[tid] = pr; sfeat[64 + tid] = pv; sfeat[128 + tid] = pr - pv;
    }
    __syncthreads();

    if (tid == 0) {
        const float temp  = fmaxf(expf(log_temp[0]), 1e-3f);
        const float scale = 1.f / ((sS + 1e-8f) * 8.f * temp);  // sqrt(C)=8
        float l[KK], mx = -1e30f;
        for (int k = 0; k < KK; k++) { l[k] = scost[k] * scale; mx = fmaxf(mx, l[k]); }
        float sum = 0.f;
        for (int k = 0; k < KK; k++) { float p = expf(l[k] - mx); l[k] = p; sum += p; }
        const float inv = 1.f / sum;
        float cdx = 0.f, cdy = 0.f, cf = 0.f;
        for (int k = 0; k < KK; k++) {
            float p = l[k] * inv;
            cf  = fmaxf(cf, p);
            cdx += p * (float)((k % 7) - 3);
            cdy += p * (float)((k / 7) - 3);
        }
        scdx = cdx; scdy = cdy; sconf = cf;
        sfeat[192] = cdx; sfeat[193] = cdy;
    }
    if (tid < 16) sfeat[194 + tid] = band_emb[band_idx[b]*16 + tid];
    __syncthreads();

    float a = b1[tid];
    for (int f = 0; f < 210; f++) a = fmaf(sfeat[f], w1[f*128 + tid], a);
    sh1[tid] = gelu_exact(a);
    __syncthreads();

    a = b2[tid];
    for (int f = 0; f < 128; f++) a = fmaf(sh1[f], w2[f*128 + tid], a);
    sh2[tid] = gelu_exact(a);
    __syncthreads();

    if (tid < 3) {
        float a3 = b3[tid];
        for (int f = 0; f < 128; f++) a3 = fmaf(sh2[f], w3[f*3 + tid], a3);
        sout3[tid] = a3;
    }
    __syncthreads();

    if (tid == 0) {
        const float dx = scdx + sout3[0];
        const float dy = scdy + sout3[1];
        const float ls = fminf(fmaxf(sout3[2], -6.f), 3.f);
        const float s0 = p2s[b*4 + 0]*dx + p2s[b*4 + 1]*dy;
        const float s1 = p2s[b*4 + 2]*dx + p2s[b*4 + 3]*dy;
        float* o = out + (size_t)b * stride;
        if (stride > 0) o[0] = dx;
        if (stride > 1) o[1] = dy;
        if (stride > 2) o[2] = s0;
        if (stride > 3) o[3] = s1;
        if (stride > 4) o[4] = ls;
        if (stride > 5) o[5] = sconf;
        for (int j = 6; j < stride; j++) o[j] = 0.f;
    }
}

// =========================== launch =========================================
extern "C" void kernel_launch(void* const* d_in, const int* in_sizes, int n_in,
                              void* d_out, int out_size)
{
    const float* rubin = (const float*)d_in[0];
    const float* vis   = (const float*)d_in[1];
    const float* p2s   = (const float*)d_in[2];
    const int*   bidx  = (const int*)  d_in[3];
    const float* wr    = (const float*)d_in[4];
    const float* wv    = (const float*)d_in[5];
    const float* lt    = (const float*)d_in[6];
    const float* bemb  = (const float*)d_in[7];
    const float* w1    = (const float*)d_in[8];
    const float* b1    = (const float*)d_in[9];
    const float* w2    = (const float*)d_in[10];
    const float* b2    = (const float*)d_in[11];
    const float* w3    = (const float*)d_in[12];
    const float* b3    = (const float*)d_in[13];
    float* out = (float*)d_out;
    const int stride = out_size / NB;

    // gauss normalizer (separable, H=W=64)
    double Sy = 0.0;
    for (int i = 0; i < 64; i++) {
        double y = -1.0 + 2.0 * (double)i / 63.0;
        Sy += exp(-2.0 * y * y);
    }
    const float inv_gsum = (float)(1.0 / (Sy * Sy));

    const int ka_smem = KA_SMEM_FLOATS * 4;   // 114432 B
    cudaFuncSetAttribute(kA, cudaFuncAttributeMaxDynamicSharedMemorySize, ka_smem);
    cudaFuncSetAttribute(kB, cudaFuncAttributeMaxDynamicSharedMemorySize, KB_SMEM_BYTES);

    kA<<<dim3(NH/2, NB), 256, ka_smem>>>(rubin, vis, wr, wv, inv_gsum);
    kB<<<dim3(8, NB), 128, KB_SMEM_BYTES>>>();
    kC<<<NB, 128>>>(p2s, bidx, lt, bemb, w1, b1, w2, b2, w3, b3, out, stride);
}

// round 14
// speedup vs baseline: 1.3015x; 1.0249x over previous
#include <cuda_runtime.h>
#include <math.h>

#define NB   128   // batch
#define NC   64    // channels
#define NH   64
#define NW   64
#define NPIX (NH*NW)
#define KK   49

typedef unsigned long long u64;
typedef unsigned u32;

// ---- packed fp32x2 helpers (sm_100+ PTX; full IEEE fp32 per lane) ----------
__device__ __forceinline__ u64 splat2(float a) {
    u64 r; asm("mov.b64 %0, {%1,%1};" : "=l"(r) : "f"(a)); return r;
}
__device__ __forceinline__ void fma2(u64& d, u64 a, u64 b) {
    asm("fma.rn.f32x2 %0, %1, %2, %0;" : "+l"(d) : "l"(a), "l"(b));
}
__device__ __forceinline__ float2 upk(u64 v) {
    float2 f; asm("mov.b64 {%0,%1}, %2;" : "=f"(f.x), "=f"(f.y) : "l"(v)); return f;
}
#define GETC(v,cc) ((cc)==0?(v).x:(cc)==1?(v).y:(cc)==2?(v).z:(v).w)

// pack two f32 -> bf16x2 (lo in low half)
__device__ __forceinline__ u32 pack_bf2(float lo, float hi) {
    u32 r; asm("cvt.rn.bf16x2.f32 %0, %1, %2;" : "=r"(r) : "f"(hi), "f"(lo)); return r;
}
// expand bf16x2 (u32) -> f32x2 (u64 register pair); exact
__device__ __forceinline__ u64 bfpair(u32 v) {
    u32 lo = v << 16, hi = v & 0xffff0000u;
    u64 r; asm("mov.b64 %0, {%1,%2};" : "=l"(r) : "r"(lo), "r"(hi)); return r;
}

// ---------------- scratch (device globals; no allocations allowed) ----------
// bf16 scratch, FLAT layout: [b][pix][64ch] -> u32 view: 32 u32 per pixel
__device__ __align__(16) u32 g_rubinw32[NB*NPIX*NC/2];
__device__ __align__(16) u32 g_visn32  [NB*NPIX*NC/2];
__device__ float g_costpart[NB*8*KK];
__device__ float g_poolr[NB*NH*NC];
__device__ float g_poolv[NB*NH*NC];
__device__ float g_Spart[NB*NH];

// =========================== Kernel A =======================================
// One block per (b, 2-row pair). 256 threads, 8 warps, TENSOR-SPECIALIZED:
// warps 0-3 -> rubin, warps 4-7 -> vis. Each warp owns 16 outputs; each
// thread owns 4 pixels -> 32 u64 f32x2 accumulators. Epilogue stores bf16.
#define OFF_WR  0
#define OFF_WV  4352
#define OFF_XR  8704
#define OFF_XV  17408
#define OFF_SQR 26112
#define OFF_SQV 26624
#define OFF_PR  27136
#define OFF_PV  27648
#define OFF_GX  28160
#define OFF_FR  28224
#define OFF_SV  28352
#define OFF_SW  28480
#define KA_SMEM_FLOATS 28608

__global__ void __launch_bounds__(256, 2)
kA(const float* __restrict__ rubin, const float* __restrict__ vis,
   const float* __restrict__ wr, const float* __restrict__ wv, float inv_gsum)
{
    extern __shared__ float sm[];
    float* sWr = sm + OFF_WR;    // [c][o], stride 68
    float* sWv = sm + OFF_WV;
    float* sXr = sm + OFF_XR;    // [pix][c], 128 pixels, stride 68
    float* sXv = sm + OFF_XV;
    float* sSQR = sm + OFF_SQR;  // [4][128]
    float* sSQV = sm + OFF_SQV;  // [4][128]
    float* sPr = sm + OFF_PR;    // [2rows][4q][64c]
    float* sPv = sm + OFF_PV;
    float* sGx = sm + OFF_GX;    // [64]
    float* sFr = sm + OFF_FR;    // [128]
    float* sSv = sm + OFF_SV;    // [128]
    float* sSw = sm + OFF_SW;    // [128]

    const int h0 = blockIdx.x * 2, b = blockIdx.y;
    const int tid = threadIdx.x;
    const int wid = tid >> 5, lane = tid & 31;
    const bool isR = (wid < 4);

    // ---- weights -> smem transposed [c][o] (coalesced global read) ----
    for (int idx = tid; idx < 4096; idx += 256) {
        int o = idx >> 6, c = idx & 63;
        sWr[c*68 + o] = wr[idx];
        sWv[c*68 + o] = wv[idx];
    }
    if (tid < 64) {
        float xxg = -1.f + 2.f * (float)tid / 63.f;
        sGx[tid] = expf(-2.f * xxg * xxg);
    }

    // ---- stage x transposed: sX[pix][c], pix = r*64 + w ----
    {
        const int w0 = tid & 63, cq = tid >> 6;
#pragma unroll
        for (int r = 0; r < 2; r++) {
            const size_t rowbase = (size_t)b*NC*NPIX + (size_t)(h0 + r)*64 + w0;
            const int pofs = (r*64 + w0)*68;
#pragma unroll
            for (int it = 0; it < 4; it++) {
                int c0 = cq*4 + it*16;
                float4 vr, vv;
                vr.x = rubin[rowbase + (size_t)(c0+0)*NPIX];
                vr.y = rubin[rowbase + (size_t)(c0+1)*NPIX];
                vr.z = rubin[rowbase + (size_t)(c0+2)*NPIX];
                vr.w = rubin[rowbase + (size_t)(c0+3)*NPIX];
                vv.x = vis  [rowbase + (size_t)(c0+0)*NPIX];
                vv.y = vis  [rowbase + (size_t)(c0+1)*NPIX];
                vv.z = vis  [rowbase + (size_t)(c0+2)*NPIX];
                vv.w = vis  [rowbase + (size_t)(c0+3)*NPIX];
                *(float4*)&sXr[pofs + c0] = vr;
                *(float4*)&sXv[pofs + c0] = vv;
            }
        }
    }
    __syncthreads();

    // ---- f32x2 register-tiled GEMM (one tensor per warp, 4 pixels/thread) --
    const int og = (wid & 3) * 16;
    const float* sX = isR ? sXr : sXv;
    const float* sW = isR ? sWr : sWv;

    u64 acc[4][8];     // [pixel][output-pair]
#pragma unroll
    for (int pp = 0; pp < 4; pp++)
#pragma unroll
        for (int j = 0; j < 8; j++) acc[pp][j] = 0ull;

#pragma unroll 2
    for (int c0 = 0; c0 < 64; c0 += 4) {
        float4 x[4];
#pragma unroll
        for (int pp = 0; pp < 4; pp++)
            x[pp] = *(const float4*)&sX[(lane + 32*pp)*68 + c0];
#pragma unroll
        for (int cc = 0; cc < 4; cc++) {
            const int c = c0 + cc;
            const ulonglong2 wa = *(const ulonglong2*)&sW[c*68 + og];
            const ulonglong2 wb = *(const ulonglong2*)&sW[c*68 + og + 4];
            const ulonglong2 wc = *(const ulonglong2*)&sW[c*68 + og + 8];
            const ulonglong2 wd = *(const ulonglong2*)&sW[c*68 + og + 12];
#pragma unroll
            for (int pp = 0; pp < 4; pp++) {
                const u64 s = splat2(GETC(x[pp], cc));
                fma2(acc[pp][0], wa.x, s); fma2(acc[pp][1], wa.y, s);
                fma2(acc[pp][2], wb.x, s); fma2(acc[pp][3], wb.y, s);
                fma2(acc[pp][4], wc.x, s); fma2(acc[pp][5], wc.y, s);
                fma2(acc[pp][6], wd.x, s); fma2(acc[pp][7], wd.y, s);
            }
        }
    }

    // ---- pool partials over raw x (still resident in sXr/sXv) ----
    {
        const int c = tid & 63, q = tid >> 6;
#pragma unroll
        for (int r = 0; r < 2; r++) {
            float pr = 0.f, pv = 0.f;
#pragma unroll
            for (int w = 0; w < 16; w++) {
                const int wcol = q*16 + w;
                const int px = r*64 + wcol;
                const float gxw = sGx[wcol];
                pr = fmaf(sXr[px*68 + c], gxw, pr);
                pv = fmaf(sXv[px*68 + c], gxw, pv);
            }
            sPr[(r*4 + q)*64 + c] = pr;
            sPv[(r*4 + q)*64 + c] = pv;
        }
    }

    // ---- per-(warp,pixel) square partials over this warp's 16 outputs ----
    {
        float* sSQ = isR ? sSQR : sSQV;
#pragma unroll
        for (int pp = 0; pp < 4; pp++) {
            float sq = 0.f;
#pragma unroll
            for (int j = 0; j < 8; j++) {
                float2 t = upk(acc[pp][j]);
                sq = fmaf(t.x, t.x, fmaf(t.y, t.y, sq));
            }
            sSQ[(wid & 3)*128 + lane + 32*pp] = sq;
        }
    }
    __syncthreads();

    if (tid < 128) {
        const int pix = tid;           // r*64 + col
        const int r = pix >> 6, col = pix & 63;
        float ssr = 0.f, ssv = 0.f;
#pragma unroll
        for (int w = 0; w < 4; w++) { ssr += sSQR[w*128 + pix]; ssv += sSQV[w*128 + pix]; }
        const float sr = 1.f / fmaxf(sqrtf(ssr), 1e-6f);
        const float sv = 1.f / fmaxf(sqrtf(ssv), 1e-6f);
        const float e  = ssr * sr * sr;
        const float yy = -1.f + 2.f * (float)(h0 + r) / 63.f;
        const float gy = expf(-2.f*yy*yy);
        const float g  = gy * sGx[col] * inv_gsum;
        const float swraw = e * g;
        sFr[pix] = sr * swraw;
        sSv[pix] = sv;
        sSw[pix] = swraw;
        const float gyn = gy * inv_gsum;
        const int c = col;
        g_poolr[(b*NH + h0 + r)*NC + c] =
            (sPr[(r*4+0)*64+c] + sPr[(r*4+1)*64+c] + sPr[(r*4+2)*64+c] + sPr[(r*4+3)*64+c]) * gyn;
        g_poolv[(b*NH + h0 + r)*NC + c] =
            (sPv[(r*4+0)*64+c] + sPv[(r*4+1)*64+c] + sPv[(r*4+2)*64+c] + sPv[(r*4+3)*64+c]) * gyn;
    }
    __syncthreads();

    if (tid < 2) {
        float s = 0.f;
        for (int i = 0; i < 64; i++) s += sSw[tid*64 + i];
        g_Spart[b*NH + h0 + tid] = s;
    }

    // ---- scale accums and re-stage into own tensor's sX (raw x now dead) ----
    {
        float* sXo = isR ? sXr : sXv;
#pragma unroll
        for (int pp = 0; pp < 4; pp++) {
            const int pix = lane + 32*pp;
            const float f = isR ? sFr[pix] : sSv[pix];
#pragma unroll
            for (int q = 0; q < 4; q++) {
                float2 ta = upk(acc[pp][2*q]), tb = upk(acc[pp][2*q+1]);
                float4 t; t.x = ta.x*f; t.y = ta.y*f; t.z = tb.x*f; t.w = tb.y*f;
                *(float4*)&sXo[pix*68 + og + 4*q] = t;
            }
        }
    }
    __syncthreads();

    // ---- bf16 convert + coalesced global stores: [b][pix][64] bf16 ----
    {
        const size_t gbase = (size_t)(b*NPIX + h0*64) * 32;   // u32 units
#pragma unroll
        for (int k = 0; k < 4; k++) {
            const int idx  = k*256 + tid;     // uint4 index 0..1023
            const int pix  = idx >> 3;
            const int part = idx & 7;         // 8-channel group
            const float* sr4 = &sXr[pix*68 + part*8];
            const float* sv4 = &sXv[pix*68 + part*8];
            uint4 orr, ovv;
            orr.x = pack_bf2(sr4[0], sr4[1]); orr.y = pack_bf2(sr4[2], sr4[3]);
            orr.z = pack_bf2(sr4[4], sr4[5]); orr.w = pack_bf2(sr4[6], sr4[7]);
            ovv.x = pack_bf2(sv4[0], sv4[1]); ovv.y = pack_bf2(sv4[2], sv4[3]);
            ovv.z = pack_bf2(sv4[4], sv4[5]); ovv.w = pack_bf2(sv4[6], sv4[7]);
            *(uint4*)&g_rubinw32[gbase + pix*32 + part*4] = orr;
            *(uint4*)&g_visn32  [gbase + pix*32 + part*4] = ovv;
        }
    }
}

// =========================== Kernel B =======================================
// Correlation costs over bf16 scratch. Block = (b, 8-row tile), 128 threads:
// col = tid>>1 (one column/thread), q = tid&1 (4-channel half of the 8-ch
// chunk). 8 chunks of 8 channels, cp.async double-buffered (16B per
// (t,col) = the full 8-ch chunk row). smem uint2 idx = t*128 + col*2 + q:
// u64-bank = (2col+q) mod 16, distinct per 16-lane phase -> conflict-free.
#define KB_CHUNK_U2 (14*128)                 // uint2 units per buffer
#define KB_SMEM_BYTES (2*KB_CHUNK_U2*8)      // 28672

__global__ void __launch_bounds__(128, 2)
kB()
{
    const int tile = blockIdx.x;            // 0..7
    const int b    = blockIdx.y;
    const int h0   = tile * 8;
    const int tid  = threadIdx.x;
    const int q    = tid & 1;               // 4-ch half (channels q*4..q*4+3)
    const int col  = tid >> 1;              // 0..63

    extern __shared__ uint2 sbuf[];         // [2][KB_CHUNK_U2]

    const u32* vbat = g_visn32   + (size_t)b*NPIX*32;
    const u32* rbat = g_rubinw32 + (size_t)b*NPIX*32;

    auto stage = [&](int ch, int bufi) {
        uint2* dst = sbuf + bufi*KB_CHUNK_U2;
        const u32* vpl = vbat + ch*4;
        for (int idx = tid; idx < 14*64; idx += 128) {
            const int c2 = idx & 63;
            const int t  = idx >> 6;
            const int gr = min(max(h0 + t - 3, 0), 63);
            const u32* src = vpl + ((size_t)(gr*64 + c2))*32;
            unsigned d = (unsigned)__cvta_generic_to_shared(&dst[t*128 + c2*2]);
            asm volatile("cp.async.cg.shared.global [%0], [%1], 16;"
                         :: "r"(d), "l"(src) : "memory");
        }
        asm volatile("cp.async.commit_group;" ::: "memory");
    };

    u64 acc2[KK];
#pragma unroll
    for (int k = 0; k < KK; k++) acc2[k] = 0ull;

    stage(0, 0);

    for (int ch = 0; ch < 8; ch++) {        // 8-channel chunks
        // rubin bf16 loads (independent of smem) - issue before the wait
        uint2 rb_bf[8];
        const u32* rpl = rbat + ch*4 + q*2;
#pragma unroll
        for (int r = 0; r < 8; r++)
            rb_bf[r] = *(const uint2*)(rpl + ((size_t)((h0 + r)*64 + col))*32);

        asm volatile("cp.async.wait_group 0;" ::: "memory");
        __syncthreads();
        if (ch < 7) stage(ch + 1, (ch + 1) & 1);

        // expand rubin to f32x2
        u64 rbf[8][2];
#pragma unroll
        for (int r = 0; r < 8; r++) {
            rbf[r][0] = bfpair(rb_bf[r].x);
            rbf[r][1] = bfpair(rb_bf[r].y);
        }

        const uint2* sv2 = sbuf + (ch & 1)*KB_CHUNK_U2;

#pragma unroll
        for (int t = 0; t < 14; t++) {
            u64 wf[7][2];
#pragma unroll
            for (int j = 0; j < 7; j++) {
                const int colw = min(max(col + j - 3, 0), 63);
                const uint2 wb = sv2[t*128 + colw*2 + q];
                wf[j][0] = bfpair(wb.x);
                wf[j][1] = bfpair(wb.y);
            }
#pragma unroll
            for (int k = 0; k < 7; k++) {
                const int r = t - k;
                if (r >= 0 && r <= 7) {
#pragma unroll
                    for (int dx = 0; dx < 7; dx++) {
                        fma2(acc2[k*7 + dx], rbf[r][0], wf[dx][0]);
                        fma2(acc2[k*7 + dx], rbf[r][1], wf[dx][1]);
                    }
                }
            }
        }
    }

    __shared__ float sred[4][KK];
    const int wid = tid >> 5, lane = tid & 31;
#pragma unroll
    for (int k = 0; k < KK; k++) {
        float2 t = upk(acc2[k]);
        float v = t.x + t.y;
#pragma unroll
        for (int off = 16; off > 0; off >>= 1) v += __shfl_down_sync(0xffffffffu, v, off);
        if (lane == 0) sred[wid][k] = v;
    }
    __syncthreads();
    if (tid < KK)
        g_costpart[(b*8 + tile)*KK + tid] =
            sred[0][tid] + sred[1][tid] + sred[2][tid] + sred[3][tid];
}

// =========================== Kernel C =======================================
__device__ __forceinline__ float gelu_exact(float x) {
    return 0.5f * x * (1.f + erff(x * 0.70710678118654752440f));
}

__global__ void __launch_bounds__(128)
kC(const float* __restrict__ p2s, const int* __restrict__ band_idx,
   const float* __restrict__ log_temp, const float* __restrict__ band_emb,
   const float* __restrict__ w1, const float* __restrict__ b1,
   const float* __restrict__ w2, const float* __restrict__ b2,
   const float* __restrict__ w3, const float* __restrict__ b3,
   float* __restrict__ out, int stride)
{
    const int b = blockIdx.x, tid = threadIdx.x;
    __shared__ float sfeat[212];
    __shared__ float scost[KK];
    __shared__ float sh1[128], sh2[128], sout3[3];
    __shared__ float sS, scdx, scdy, sconf;

    if (tid == 0) {
        float s = 0.f;
        for (int h = 0; h < NH; h++) s += g_Spart[b*NH + h];
        sS = s;
    }
    if (tid < KK) {
        float c = 0.f;
        for (int t = 0; t < 8; t++) c += g_costpart[(b*8 + t)*KK + tid];
        scost[tid] = c;
    }
    if (tid < 64) {
        float pr = 0.f, pv = 0.f;
        for (int h = 0; h < NH; h++) {
            pr += g_poolr[(b*NH + h)*NC + tid];
            pv += g_poolv[(b*NH + h)*NC + tid];
        }
        sfeat[tid] = pr; sfeat[64 + tid] = pv; sfeat[128 + tid] = pr - pv;
    }
    __syncthreads();

    if (tid == 0) {
        const float temp  = fmaxf(expf(log_temp[0]), 1e-3f);
        const float scale = 1.f / ((sS + 1e-8f) * 8.f * temp);  // sqrt(C)=8
        float l[KK], mx = -1e30f;
        for (int k = 0; k < KK; k++) { l[k] = scost[k] * scale; mx = fmaxf(mx, l[k]); }
        float sum = 0.f;
        for (int k = 0; k < KK; k++) { float p = expf(l[k] - mx); l[k] = p; sum += p; }
        const float inv = 1.f / sum;
        float cdx = 0.f, cdy = 0.f, cf = 0.f;
        for (int k = 0; k < KK; k++) {
            float p = l[k] * inv;
            cf  = fmaxf(cf, p);
            cdx += p * (float)((k % 7) - 3);
            cdy += p * (float)((k / 7) - 3);
        }
        scdx = cdx; scdy = cdy; sconf = cf;
        sfeat[192] = cdx; sfeat[193] = cdy;
    }
    if (tid < 16) sfeat[194 + tid] = band_emb[band_idx[b]*16 + tid];
    __syncthreads();

    float a = b1[tid];
    for (int f = 0; f < 210; f++) a = fmaf(sfeat[f], w1[f*128 + tid], a);
    sh1[tid] = gelu_exact(a);
    __syncthreads();

    a = b2[tid];
    for (int f = 0; f < 128; f++) a = fmaf(sh1[f], w2[f*128 + tid], a);
    sh2[tid] = gelu_exact(a);
    __syncthreads();

    if (tid < 3) {
        float a3 = b3[tid];
        for (int f = 0; f < 128; f++) a3 = fmaf(sh2[f], w3[f*3 + tid], a3);
        sout3[tid] = a3;
    }
    __syncthreads();

    if (tid == 0) {
        const float dx = scdx + sout3[0];
        const float dy = scdy + sout3[1];
        const float ls = fminf(fmaxf(sout3[2], -6.f), 3.f);
        const float s0 = p2s[b*4 + 0]*dx + p2s[b*4 + 1]*dy;
        const float s1 = p2s[b*4 + 2]*dx + p2s[b*4 + 3]*dy;
        float* o = out + (size_t)b * stride;
        if (stride > 0) o[0] = dx;
        if (stride > 1) o[1] = dy;
        if (stride > 2) o[2] = s0;
        if (stride > 3) o[3] = s1;
        if (stride > 4) o[4] = ls;
        if (stride > 5) o[5] = sconf;
        for (int j = 6; j < stride; j++) o[j] = 0.f;
    }
}

// =========================== launch =========================================
extern "C" void kernel_launch(void* const* d_in, const int* in_sizes, int n_in,
                              void* d_out, int out_size)
{
    const float* rubin = (const float*)d_in[0];
    const float* vis   = (const float*)d_in[1];
    const float* p2s   = (const float*)d_in[2];
    const int*   bidx  = (const int*)  d_in[3];
    const float* wr    = (const float*)d_in[4];
    const float* wv    = (const float*)d_in[5];
    const float* lt    = (const float*)d_in[6];
    const float* bemb  = (const float*)d_in[7];
    const float* w1    = (const float*)d_in[8];
    const float* b1    = (const float*)d_in[9];
    const float* w2    = (const float*)d_in[10];
    const float* b2    = (const float*)d_in[11];
    const float* w3    = (const float*)d_in[12];
    const float* b3    = (const float*)d_in[13];
    float* out = (float*)d_out;
    const int stride = out_size / NB;

    // gauss normalizer (separable, H=W=64)
    double Sy = 0.0;
    for (int i = 0; i < 64; i++) {
        double y = -1.0 + 2.0 * (double)i / 63.0;
        Sy += exp(-2.0 * y * y);
    }
    const float inv_gsum = (float)(1.0 / (Sy * Sy));

    const int ka_smem = KA_SMEM_FLOATS * 4;   // 114432 B
    cudaFuncSetAttribute(kA, cudaFuncAttributeMaxDynamicSharedMemorySize, ka_smem);
    cudaFuncSetAttribute(kB, cudaFuncAttributeMaxDynamicSharedMemorySize, KB_SMEM_BYTES);

    kA<<<dim3(NH/2, NB), 256, ka_smem>>>(rubin, vis, wr, wv, inv_gsum);
    kB<<<dim3(8, NB), 128, KB_SMEM_BYTES>>>();
    kC<<<NB, 128>>>(p2s, bidx, lt, bemb, w1, b1, w2, b2, w3, b3, out, stride);
}

// round 16
// speedup vs baseline: 2.0815x; 1.5993x over previous
#include <cuda_runtime.h>
#include <math.h>

#define NB   128
#define NC   64
#define NH   64
#define NW   64
#define NPIX (NH*NW)
#define KK   49

typedef unsigned long long u64;
typedef unsigned u32;

// ---- packed fp32x2 helpers ------------------------------------------------
__device__ __forceinline__ void fma2(u64& d, u64 a, u64 b) {
    asm("fma.rn.f32x2 %0, %1, %2, %0;" : "+l"(d) : "l"(a), "l"(b));
}
__device__ __forceinline__ float2 upk(u64 v) {
    float2 f; asm("mov.b64 {%0,%1}, %2;" : "=f"(f.x), "=f"(f.y) : "l"(v)); return f;
}
__device__ __forceinline__ u32 pack_bf2(float lo, float hi) {
    u32 r; asm("cvt.rn.bf16x2.f32 %0, %1, %2;" : "=r"(r) : "f"(hi), "f"(lo)); return r;
}
__device__ __forceinline__ u64 bfpair(u32 v) {
    u32 lo = v << 16, hi = v & 0xffff0000u;
    u64 r; asm("mov.b64 %0, {%1,%2};" : "=l"(r) : "r"(lo), "r"(hi)); return r;
}
// bf16 m16n8k16 MMA (sm_80+; plain sm_103-safe)
__device__ __forceinline__ void mma16816(float* c, const u32* a, u32 b0, u32 b1) {
    asm volatile(
        "mma.sync.aligned.m16n8k16.row.col.f32.bf16.bf16.f32 "
        "{%0,%1,%2,%3}, {%4,%5,%6,%7}, {%8,%9}, {%0,%1,%2,%3};"
        : "+f"(c[0]), "+f"(c[1]), "+f"(c[2]), "+f"(c[3])
        : "r"(a[0]), "r"(a[1]), "r"(a[2]), "r"(a[3]), "r"(b0), "r"(b1));
}

// ---------------- scratch (device globals) ----------------------------------
// bf16 scratch, FLAT layout: [b][pix][64ch] -> u32 view: 32 u32 per pixel
__device__ __align__(16) u32 g_rubinw32[NB*NPIX*NC/2];
__device__ __align__(16) u32 g_visn32  [NB*NPIX*NC/2];
__device__ float g_costpart[NB*8*KK];
__device__ float g_poolr[NB*NH*NC];
__device__ float g_poolv[NB*NH*NC];
__device__ float g_Spart[NB*NH];

// =========================== Kernel A (mma.sync bf16) =======================
// One block per (b, 2-row pair), 256 threads, 8 warps. Warps 0-3 rubin,
// 4-7 vis; each warp owns 32 pixels x 64 outputs via 64x HMMA.16816.
// X staged as bf16 channel-pairs [pix][36 u32], W as [o][36 u32] (stride 36
// -> conflict-free fragment loads). Pools fp32 from raw loads (shuffles).
#define SM_GX   0
#define SM_PR   256
#define SM_PV   768
#define SM_SW   1280
#define SM_XR   2048
#define SM_XV   20480
#define SM_WR   38912
#define SM_WV   48128
#define KA_SMEM_BYTES 57344

__global__ void __launch_bounds__(256, 2)
kA(const float* __restrict__ rubin, const float* __restrict__ vis,
   const float* __restrict__ wr, const float* __restrict__ wv, float inv_gsum)
{
    extern __shared__ char smc[];
    const int h0 = blockIdx.x*2, b = blockIdx.y;
    const int tid = threadIdx.x, wid = tid >> 5, lane = tid & 31;
    const bool isR = (wid < 4);

    float* sGx = (float*)(smc + SM_GX);
    float* sPr = (float*)(smc + SM_PR);   // [c][2]
    float* sPv = (float*)(smc + SM_PV);
    float* sSw = (float*)(smc + SM_SW);   // [128]

    if (tid < 64) {
        float xx = -1.f + 2.f*(float)tid/63.f;
        sGx[tid] = expf(-2.f*xx*xx);
    }
    __syncthreads();

    // ---- stage X bf16 pairs + fp32 pools ----
    {
        const size_t ibase = (size_t)b*NC*NPIX + (size_t)h0*64;
#pragma unroll
        for (int tsel = 0; tsel < 2; tsel++) {
            const float* in = tsel ? vis : rubin;
            float* sP = tsel ? sPv : sPr;
            u32* sXb = (u32*)(smc + (tsel ? SM_XV : SM_XR));
#pragma unroll
            for (int it = 0; it < 8; it++) {
                const int e = it*256 + tid;
                const int p = e & 31, r = (e>>5)&1, cp = e>>6;
                const int c0 = 2*cp, c1 = c0 + 1;
                const float* rowb = in + ibase + (size_t)r*64;
                const float x0a = rowb[(size_t)c0*NPIX + p];
                const float x0b = rowb[(size_t)c0*NPIX + p + 32];
                const float x1a = rowb[(size_t)c1*NPIX + p];
                const float x1b = rowb[(size_t)c1*NPIX + p + 32];
                float pl0 = x0a*sGx[p] + x0b*sGx[p+32];
                float pl1 = x1a*sGx[p] + x1b*sGx[p+32];
#pragma unroll
                for (int off = 16; off > 0; off >>= 1) {
                    pl0 += __shfl_down_sync(0xffffffffu, pl0, off);
                    pl1 += __shfl_down_sync(0xffffffffu, pl1, off);
                }
                if (lane == 0) { sP[c0*2 + r] = pl0; sP[c1*2 + r] = pl1; }
                sXb[(r*64 + p)*36 + cp]      = pack_bf2(x0a, x1a);
                sXb[(r*64 + p + 32)*36 + cp] = pack_bf2(x0b, x1b);
            }
        }
        // weights -> bf16 pairs [o][36]
        u32* sWbR = (u32*)(smc + SM_WR);
        u32* sWbV = (u32*)(smc + SM_WV);
#pragma unroll
        for (int it = 0; it < 8; it++) {
            const int e = it*256 + tid;
            const int cp = e & 31, o = e >> 5;
            sWbR[o*36 + cp] = pack_bf2(wr[o*64 + 2*cp], wr[o*64 + 2*cp + 1]);
            sWbV[o*36 + cp] = pack_bf2(wv[o*64 + 2*cp], wv[o*64 + 2*cp + 1]);
        }
    }
    __syncthreads();

    // ---- HMMA GEMM: D[32pix x 64out] per warp ----
    const u32* sXb = (const u32*)(smc + (isR ? SM_XR : SM_XV));
    const u32* sWb = (const u32*)(smc + (isR ? SM_WR : SM_WV));
    const int pixbase = (wid & 3) * 32;
    const int g = lane >> 2, tg = lane & 3;

    float c[2][8][4];
#pragma unroll
    for (int mt = 0; mt < 2; mt++)
#pragma unroll
        for (int nt = 0; nt < 8; nt++)
#pragma unroll
            for (int j = 0; j < 4; j++) c[mt][nt][j] = 0.f;

#pragma unroll
    for (int ks = 0; ks < 4; ks++) {
        u32 a[2][4];
#pragma unroll
        for (int mt = 0; mt < 2; mt++) {
            const int rowA = pixbase + mt*16 + g;
            a[mt][0] = sXb[rowA*36      + ks*8 + tg];
            a[mt][1] = sXb[(rowA+8)*36  + ks*8 + tg];
            a[mt][2] = sXb[rowA*36      + ks*8 + tg + 4];
            a[mt][3] = sXb[(rowA+8)*36  + ks*8 + tg + 4];
        }
#pragma unroll
        for (int nt = 0; nt < 8; nt++) {
            const u32 b0 = sWb[(nt*8 + g)*36 + ks*8 + tg];
            const u32 b1 = sWb[(nt*8 + g)*36 + ks*8 + tg + 4];
            mma16816(c[0][nt], a[0], b0, b1);
            mma16816(c[1][nt], a[1], b0, b1);
        }
    }

    // ---- epilogue: per-pixel normalize + bf16 pack (overlay own X tile) ----
    {
        u32* sOut = (u32*)(smc + (isR ? SM_XR : SM_XV));
#pragma unroll
        for (int mt = 0; mt < 2; mt++) {
            const int row0 = pixbase + mt*16 + g;      // and row0+8
            float sq0 = 0.f, sq1 = 0.f;
#pragma unroll
            for (int nt = 0; nt < 8; nt++) {
                sq0 = fmaf(c[mt][nt][0], c[mt][nt][0], fmaf(c[mt][nt][1], c[mt][nt][1], sq0));
                sq1 = fmaf(c[mt][nt][2], c[mt][nt][2], fmaf(c[mt][nt][3], c[mt][nt][3], sq1));
            }
            sq0 += __shfl_xor_sync(0xffffffffu, sq0, 1);
            sq0 += __shfl_xor_sync(0xffffffffu, sq0, 2);
            sq1 += __shfl_xor_sync(0xffffffffu, sq1, 1);
            sq1 += __shfl_xor_sync(0xffffffffu, sq1, 2);

            float f0, f1;
            {
                const float s0 = 1.f / fmaxf(sqrtf(sq0), 1e-6f);
                const float s1 = 1.f / fmaxf(sqrtf(sq1), 1e-6f);
                if (isR) {
                    const int rA = row0 >> 6, colA = row0 & 63;
                    const int rB = (row0+8) >> 6, colB = (row0+8) & 63;
                    const float yA = -1.f + 2.f*(float)(h0 + rA)/63.f;
                    const float yB = -1.f + 2.f*(float)(h0 + rB)/63.f;
                    const float gA = expf(-2.f*yA*yA) * sGx[colA] * inv_gsum;
                    const float gB = expf(-2.f*yB*yB) * sGx[colB] * inv_gsum;
                    const float swA = sq0*s0*s0*gA;
                    const float swB = sq1*s1*s1*gB;
                    if (tg == 0) { sSw[row0] = swA; sSw[row0+8] = swB; }
                    f0 = s0 * swA; f1 = s1 * swB;
                } else {
                    f0 = s0; f1 = s1;
                }
            }
#pragma unroll
            for (int nt = 0; nt < 8; nt++) {
                sOut[row0*36 + nt*4 + tg] =
                    pack_bf2(c[mt][nt][0]*f0, c[mt][nt][1]*f0);
                sOut[(row0+8)*36 + nt*4 + tg] =
                    pack_bf2(c[mt][nt][2]*f1, c[mt][nt][3]*f1);
            }
        }
    }
    __syncthreads();

    // ---- Spart + pools ----
    if (tid < 2) {
        float su = 0.f;
        for (int i = 0; i < 64; i++) su += sSw[tid*64 + i];
        g_Spart[b*NH + h0 + tid] = su;
    }
    if (tid < 128) {
        const int cch = tid & 63, r = tid >> 6;
        const float yy = -1.f + 2.f*(float)(h0 + r)/63.f;
        const float gyn = expf(-2.f*yy*yy) * inv_gsum;
        g_poolr[(b*NH + h0 + r)*NC + cch] = sPr[cch*2 + r] * gyn;
        g_poolv[(b*NH + h0 + r)*NC + cch] = sPv[cch*2 + r] * gyn;
    }

    // ---- coalesced STG of bf16 scratch: [b][pix][32 u32] ----
    {
        const size_t gb = (size_t)(b*NPIX + h0*64) * 32;
        const u32* oR = (const u32*)(smc + SM_XR);
        const u32* oV = (const u32*)(smc + SM_XV);
#pragma unroll
        for (int it = 0; it < 16; it++) {
            const int idx = it*256 + tid;       // 4096 u32 per tensor
            const int pix = idx >> 5, j = idx & 31;
            g_rubinw32[gb + pix*32 + j] = oR[pix*36 + j];
            g_visn32  [gb + pix*32 + j] = oV[pix*36 + j];
        }
    }
}

// =========================== Kernel B (r14, unchanged) ======================
#define KB_CHUNK_U2 (14*128)
#define KB_SMEM_BYTES (2*KB_CHUNK_U2*8)      // 28672

__global__ void __launch_bounds__(128, 2)
kB()
{
    const int tile = blockIdx.x;
    const int b    = blockIdx.y;
    const int h0   = tile * 8;
    const int tid  = threadIdx.x;
    const int q    = tid & 1;
    const int col  = tid >> 1;

    extern __shared__ uint2 sbuf[];

    const u32* vbat = g_visn32   + (size_t)b*NPIX*32;
    const u32* rbat = g_rubinw32 + (size_t)b*NPIX*32;

    auto stage = [&](int ch, int bufi) {
        uint2* dst = sbuf + bufi*KB_CHUNK_U2;
        const u32* vpl = vbat + ch*4;
        for (int idx = tid; idx < 14*64; idx += 128) {
            const int c2 = idx & 63;
            const int t  = idx >> 6;
            const int gr = min(max(h0 + t - 3, 0), 63);
            const u32* src = vpl + ((size_t)(gr*64 + c2))*32;
            unsigned d = (unsigned)__cvta_generic_to_shared(&dst[t*128 + c2*2]);
            asm volatile("cp.async.cg.shared.global [%0], [%1], 16;"
                         :: "r"(d), "l"(src) : "memory");
        }
        asm volatile("cp.async.commit_group;" ::: "memory");
    };

    u64 acc2[KK];
#pragma unroll
    for (int k = 0; k < KK; k++) acc2[k] = 0ull;

    stage(0, 0);

    for (int ch = 0; ch < 8; ch++) {
        uint2 rb_bf[8];
        const u32* rpl = rbat + ch*4 + q*2;
#pragma unroll
        for (int r = 0; r < 8; r++)
            rb_bf[r] = *(const uint2*)(rpl + ((size_t)((h0 + r)*64 + col))*32);

        asm volatile("cp.async.wait_group 0;" ::: "memory");
        __syncthreads();
        if (ch < 7) stage(ch + 1, (ch + 1) & 1);

        u64 rbf[8][2];
#pragma unroll
        for (int r = 0; r < 8; r++) {
            rbf[r][0] = bfpair(rb_bf[r].x);
            rbf[r][1] = bfpair(rb_bf[r].y);
        }

        const uint2* sv2 = sbuf + (ch & 1)*KB_CHUNK_U2;

#pragma unroll
        for (int t = 0; t < 14; t++) {
            u64 wf[7][2];
#pragma unroll
            for (int j = 0; j < 7; j++) {
                const int colw = min(max(col + j - 3, 0), 63);
                const uint2 wb = sv2[t*128 + colw*2 + q];
                wf[j][0] = bfpair(wb.x);
                wf[j][1] = bfpair(wb.y);
            }
#pragma unroll
            for (int k = 0; k < 7; k++) {
                const int r = t - k;
                if (r >= 0 && r <= 7) {
#pragma unroll
                    for (int dx = 0; dx < 7; dx++) {
                        fma2(acc2[k*7 + dx], rbf[r][0], wf[dx][0]);
                        fma2(acc2[k*7 + dx], rbf[r][1], wf[dx][1]);
                    }
                }
            }
        }
    }

    __shared__ float sred[4][KK];
    const int wid = tid >> 5, lane = tid & 31;
#pragma unroll
    for (int k = 0; k < KK; k++) {
        float2 t = upk(acc2[k]);
        float v = t.x + t.y;
#pragma unroll
        for (int off = 16; off > 0; off >>= 1) v += __shfl_down_sync(0xffffffffu, v, off);
        if (lane == 0) sred[wid][k] = v;
    }
    __syncthreads();
    if (tid < KK)
        g_costpart[(b*8 + tile)*KK + tid] =
            sred[0][tid] + sred[1][tid] + sred[2][tid] + sred[3][tid];
}

// =========================== Kernel C (unchanged) ===========================
__device__ __forceinline__ float gelu_exact(float x) {
    return 0.5f * x * (1.f + erff(x * 0.70710678118654752440f));
}

__global__ void __launch_bounds__(128)
kC(const float* __restrict__ p2s, const int* __restrict__ band_idx,
   const float* __restrict__ log_temp, const float* __restrict__ band_emb,
   const float* __restrict__ w1, const float* __restrict__ b1,
   const float* __restrict__ w2, const float* __restrict__ b2,
   const float* __restrict__ w3, const float* __restrict__ b3,
   float* __restrict__ out, int stride)
{
    const int b = blockIdx.x, tid = threadIdx.x;
    __shared__ float sfeat[212];
    __shared__ float scost[KK];
    __shared__ float sh1[128], sh2[128], sout3[3];
    __shared__ float sS, scdx, scdy, sconf;

    if (tid == 0) {
        float s = 0.f;
        for (int h = 0; h < NH; h++) s += g_Spart[b*NH + h];
        sS = s;
    }
    if (tid < KK) {
        float c = 0.f;
        for (int t = 0; t < 8; t++) c += g_costpart[(b*8 + t)*KK + tid];
        scost[tid] = c;
    }
    if (tid < 64) {
        float pr = 0.f, pv = 0.f;
        for (int h = 0; h < NH; h++) {
            pr += g_poolr[(b*NH + h)*NC + tid];
            pv += g_poolv[(b*NH + h)*NC + tid];
        }
        sfeat[tid] = pr; sfeat[64 + tid] = pv; sfeat[128 + tid] = pr - pv;
    }
    __syncthreads();

    if (tid == 0) {
        const float temp  = fmaxf(expf(log_temp[0]), 1e-3f);
        const float scale = 1.f / ((sS + 1e-8f) * 8.f * temp);
        float l[KK], mx = -1e30f;
        for (int k = 0; k < KK; k++) { l[k] = scost[k] * scale; mx = fmaxf(mx, l[k]); }
        float sum = 0.f;
        for (int k = 0; k < KK; k++) { float p = expf(l[k] - mx); l[k] = p; sum += p; }
        const float inv = 1.f / sum;
        float cdx = 0.f, cdy = 0.f, cf = 0.f;
        for (int k = 0; k < KK; k++) {
            float p = l[k] * inv;
            cf  = fmaxf(cf, p);
            cdx += p * (float)((k % 7) - 3);
            cdy += p * (float)((k / 7) - 3);
        }
        scdx = cdx; scdy = cdy; sconf = cf;
        sfeat[192] = cdx; sfeat[193] = cdy;
    }
    if (tid < 16) sfeat[194 + tid] = band_emb[band_idx[b]*16 + tid];
    __syncthreads();

    float a = b1[tid];
    for (int f = 0; f < 210; f++) a = fmaf(sfeat[f], w1[f*128 + tid], a);
    sh1[tid] = gelu_exact(a);
    __syncthreads();

    a = b2[tid];
    for (int f = 0; f < 128; f++) a = fmaf(sh1[f], w2[f*128 + tid], a);
    sh2[tid] = gelu_exact(a);
    __syncthreads();

    if (tid < 3) {
        float a3 = b3[tid];
        for (int f = 0; f < 128; f++) a3 = fmaf(sh2[f], w3[f*3 + tid], a3);
        sout3[tid] = a3;
    }
    __syncthreads();

    if (tid == 0) {
        const float dx = scdx + sout3[0];
        const float dy = scdy + sout3[1];
        const float ls = fminf(fmaxf(sout3[2], -6.f), 3.f);
        const float s0 = p2s[b*4 + 0]*dx + p2s[b*4 + 1]*dy;
        const float s1 = p2s[b*4 + 2]*dx + p2s[b*4 + 3]*dy;
        float* o = out + (size_t)b * stride;
        if (stride > 0) o[0] = dx;
        if (stride > 1) o[1] = dy;
        if (stride > 2) o[2] = s0;
        if (stride > 3) o[3] = s1;
        if (stride > 4) o[4] = ls;
        if (stride > 5) o[5] = sconf;
        for (int j = 6; j < stride; j++) o[j] = 0.f;
    }
}

// =========================== launch =========================================
extern "C" void kernel_launch(void* const* d_in, const int* in_sizes, int n_in,
                              void* d_out, int out_size)
{
    const float* rubin = (const float*)d_in[0];
    const float* vis   = (const float*)d_in[1];
    const float* p2s   = (const float*)d_in[2];
    const int*   bidx  = (const int*)  d_in[3];
    const float* wr    = (const float*)d_in[4];
    const float* wv    = (const float*)d_in[5];
    const float* lt    = (const float*)d_in[6];
    const float* bemb  = (const float*)d_in[7];
    const float* w1    = (const float*)d_in[8];
    const float* b1    = (const float*)d_in[9];
    const float* w2    = (const float*)d_in[10];
    const float* b2    = (const float*)d_in[11];
    const float* w3    = (const float*)d_in[12];
    const float* b3    = (const float*)d_in[13];
    float* out = (float*)d_out;
    const int stride = out_size / NB;

    double Sy = 0.0;
    for (int i = 0; i < 64; i++) {
        double y = -1.0 + 2.0 * (double)i / 63.0;
        Sy += exp(-2.0 * y * y);
    }
    const float inv_gsum = (float)(1.0 / (Sy * Sy));

    cudaFuncSetAttribute(kA, cudaFuncAttributeMaxDynamicSharedMemorySize, KA_SMEM_BYTES);
    cudaFuncSetAttribute(kB, cudaFuncAttributeMaxDynamicSharedMemorySize, KB_SMEM_BYTES);

    kA<<<dim3(NH/2, NB), 256, KA_SMEM_BYTES>>>(rubin, vis, wr, wv, inv_gsum);
    kB<<<dim3(8, NB), 128, KB_SMEM_BYTES>>>();
    kC<<<NB, 128>>>(p2s, bidx, lt, bemb, w1, b1, w2, b2, w3, b3, out, stride);
}

// round 17
// speedup vs baseline: 2.4403x; 1.1724x over previous
#include <cuda_runtime.h>
#include <math.h>

#define NB   128
#define NC   64
#define NH   64
#define NW   64
#define NPIX (NH*NW)
#define KK   49

typedef unsigned long long u64;
typedef unsigned u32;

// ---- helpers ---------------------------------------------------------------
__device__ __forceinline__ float2 upk(u64 v) {
    float2 f; asm("mov.b64 {%0,%1}, %2;" : "=f"(f.x), "=f"(f.y) : "l"(v)); return f;
}
__device__ __forceinline__ u32 pack_bf2(float lo, float hi) {
    u32 r; asm("cvt.rn.bf16x2.f32 %0, %1, %2;" : "=r"(r) : "f"(hi), "f"(lo)); return r;
}
__device__ __forceinline__ u64 bfpair(u32 v) {
    u32 lo = v << 16, hi = v & 0xffff0000u;
    u64 r; asm("mov.b64 %0, {%1,%2};" : "=l"(r) : "r"(lo), "r"(hi)); return r;
}
// bf16 m16n8k16 MMA (sm_80+; plain sm_103-safe)
__device__ __forceinline__ void mma16816(float* c, const u32* a, u32 b0, u32 b1) {
    asm volatile(
        "mma.sync.aligned.m16n8k16.row.col.f32.bf16.bf16.f32 "
        "{%0,%1,%2,%3}, {%4,%5,%6,%7}, {%8,%9}, {%0,%1,%2,%3};"
        : "+f"(c[0]), "+f"(c[1]), "+f"(c[2]), "+f"(c[3])
        : "r"(a[0]), "r"(a[1]), "r"(a[2]), "r"(a[3]), "r"(b0), "r"(b1));
}

// ---------------- scratch (device globals) ----------------------------------
// bf16 scratch, FLAT layout: [b][pix][64ch] -> u32 view: 32 u32 per pixel
__device__ __align__(16) u32 g_rubinw32[NB*NPIX*NC/2];
__device__ __align__(16) u32 g_visn32  [NB*NPIX*NC/2];
__device__ float g_costpart[NB*8*KK];
__device__ float g_poolr[NB*NH*NC];
__device__ float g_poolv[NB*NH*NC];
__device__ float g_Spart[NB*NH];

// =========================== Kernel A (r16, unchanged) ======================
#define SM_GX   0
#define SM_PR   256
#define SM_PV   768
#define SM_SW   1280
#define SM_XR   2048
#define SM_XV   20480
#define SM_WR   38912
#define SM_WV   48128
#define KA_SMEM_BYTES 57344

__global__ void __launch_bounds__(256, 2)
kA(const float* __restrict__ rubin, const float* __restrict__ vis,
   const float* __restrict__ wr, const float* __restrict__ wv, float inv_gsum)
{
    extern __shared__ char smc[];
    const int h0 = blockIdx.x*2, b = blockIdx.y;
    const int tid = threadIdx.x, wid = tid >> 5, lane = tid & 31;
    const bool isR = (wid < 4);

    float* sGx = (float*)(smc + SM_GX);
    float* sPr = (float*)(smc + SM_PR);
    float* sPv = (float*)(smc + SM_PV);
    float* sSw = (float*)(smc + SM_SW);

    if (tid < 64) {
        float xx = -1.f + 2.f*(float)tid/63.f;
        sGx[tid] = expf(-2.f*xx*xx);
    }
    __syncthreads();

    {
        const size_t ibase = (size_t)b*NC*NPIX + (size_t)h0*64;
#pragma unroll
        for (int tsel = 0; tsel < 2; tsel++) {
            const float* in = tsel ? vis : rubin;
            float* sP = tsel ? sPv : sPr;
            u32* sXb = (u32*)(smc + (tsel ? SM_XV : SM_XR));
#pragma unroll
            for (int it = 0; it < 8; it++) {
                const int e = it*256 + tid;
                const int p = e & 31, r = (e>>5)&1, cp = e>>6;
                const int c0 = 2*cp, c1 = c0 + 1;
                const float* rowb = in + ibase + (size_t)r*64;
                const float x0a = rowb[(size_t)c0*NPIX + p];
                const float x0b = rowb[(size_t)c0*NPIX + p + 32];
                const float x1a = rowb[(size_t)c1*NPIX + p];
                const float x1b = rowb[(size_t)c1*NPIX + p + 32];
                float pl0 = x0a*sGx[p] + x0b*sGx[p+32];
                float pl1 = x1a*sGx[p] + x1b*sGx[p+32];
#pragma unroll
                for (int off = 16; off > 0; off >>= 1) {
                    pl0 += __shfl_down_sync(0xffffffffu, pl0, off);
                    pl1 += __shfl_down_sync(0xffffffffu, pl1, off);
                }
                if (lane == 0) { sP[c0*2 + r] = pl0; sP[c1*2 + r] = pl1; }
                sXb[(r*64 + p)*36 + cp]      = pack_bf2(x0a, x1a);
                sXb[(r*64 + p + 32)*36 + cp] = pack_bf2(x0b, x1b);
            }
        }
        u32* sWbR = (u32*)(smc + SM_WR);
        u32* sWbV = (u32*)(smc + SM_WV);
#pragma unroll
        for (int it = 0; it < 8; it++) {
            const int e = it*256 + tid;
            const int cp = e & 31, o = e >> 5;
            sWbR[o*36 + cp] = pack_bf2(wr[o*64 + 2*cp], wr[o*64 + 2*cp + 1]);
            sWbV[o*36 + cp] = pack_bf2(wv[o*64 + 2*cp], wv[o*64 + 2*cp + 1]);
        }
    }
    __syncthreads();

    const u32* sXb = (const u32*)(smc + (isR ? SM_XR : SM_XV));
    const u32* sWb = (const u32*)(smc + (isR ? SM_WR : SM_WV));
    const int pixbase = (wid & 3) * 32;
    const int g = lane >> 2, tg = lane & 3;

    float c[2][8][4];
#pragma unroll
    for (int mt = 0; mt < 2; mt++)
#pragma unroll
        for (int nt = 0; nt < 8; nt++)
#pragma unroll
            for (int j = 0; j < 4; j++) c[mt][nt][j] = 0.f;

#pragma unroll
    for (int ks = 0; ks < 4; ks++) {
        u32 a[2][4];
#pragma unroll
        for (int mt = 0; mt < 2; mt++) {
            const int rowA = pixbase + mt*16 + g;
            a[mt][0] = sXb[rowA*36      + ks*8 + tg];
            a[mt][1] = sXb[(rowA+8)*36  + ks*8 + tg];
            a[mt][2] = sXb[rowA*36      + ks*8 + tg + 4];
            a[mt][3] = sXb[(rowA+8)*36  + ks*8 + tg + 4];
        }
#pragma unroll
        for (int nt = 0; nt < 8; nt++) {
            const u32 b0 = sWb[(nt*8 + g)*36 + ks*8 + tg];
            const u32 b1 = sWb[(nt*8 + g)*36 + ks*8 + tg + 4];
            mma16816(c[0][nt], a[0], b0, b1);
            mma16816(c[1][nt], a[1], b0, b1);
        }
    }

    {
        u32* sOut = (u32*)(smc + (isR ? SM_XR : SM_XV));
#pragma unroll
        for (int mt = 0; mt < 2; mt++) {
            const int row0 = pixbase + mt*16 + g;
            float sq0 = 0.f, sq1 = 0.f;
#pragma unroll
            for (int nt = 0; nt < 8; nt++) {
                sq0 = fmaf(c[mt][nt][0], c[mt][nt][0], fmaf(c[mt][nt][1], c[mt][nt][1], sq0));
                sq1 = fmaf(c[mt][nt][2], c[mt][nt][2], fmaf(c[mt][nt][3], c[mt][nt][3], sq1));
            }
            sq0 += __shfl_xor_sync(0xffffffffu, sq0, 1);
            sq0 += __shfl_xor_sync(0xffffffffu, sq0, 2);
            sq1 += __shfl_xor_sync(0xffffffffu, sq1, 1);
            sq1 += __shfl_xor_sync(0xffffffffu, sq1, 2);

            float f0, f1;
            {
                const float s0 = 1.f / fmaxf(sqrtf(sq0), 1e-6f);
                const float s1 = 1.f / fmaxf(sqrtf(sq1), 1e-6f);
                if (isR) {
                    const int rA = row0 >> 6, colA = row0 & 63;
                    const int rB = (row0+8) >> 6, colB = (row0+8) & 63;
                    const float yA = -1.f + 2.f*(float)(h0 + rA)/63.f;
                    const float yB = -1.f + 2.f*(float)(h0 + rB)/63.f;
                    const float gA = expf(-2.f*yA*yA) * sGx[colA] * inv_gsum;
                    const float gB = expf(-2.f*yB*yB) * sGx[colB] * inv_gsum;
                    const float swA = sq0*s0*s0*gA;
                    const float swB = sq1*s1*s1*gB;
                    if (tg == 0) { sSw[row0] = swA; sSw[row0+8] = swB; }
                    f0 = s0 * swA; f1 = s1 * swB;
                } else {
                    f0 = s0; f1 = s1;
                }
            }
#pragma unroll
            for (int nt = 0; nt < 8; nt++) {
                sOut[row0*36 + nt*4 + tg] =
                    pack_bf2(c[mt][nt][0]*f0, c[mt][nt][1]*f0);
                sOut[(row0+8)*36 + nt*4 + tg] =
                    pack_bf2(c[mt][nt][2]*f1, c[mt][nt][3]*f1);
            }
        }
    }
    __syncthreads();

    if (tid < 2) {
        float su = 0.f;
        for (int i = 0; i < 64; i++) su += sSw[tid*64 + i];
        g_Spart[b*NH + h0 + tid] = su;
    }
    if (tid < 128) {
        const int cch = tid & 63, r = tid >> 6;
        const float yy = -1.f + 2.f*(float)(h0 + r)/63.f;
        const float gyn = expf(-2.f*yy*yy) * inv_gsum;
        g_poolr[(b*NH + h0 + r)*NC + cch] = sPr[cch*2 + r] * gyn;
        g_poolv[(b*NH + h0 + r)*NC + cch] = sPv[cch*2 + r] * gyn;
    }

    {
        const size_t gb = (size_t)(b*NPIX + h0*64) * 32;
        const u32* oR = (const u32*)(smc + SM_XR);
        const u32* oV = (const u32*)(smc + SM_XV);
#pragma unroll
        for (int it = 0; it < 16; it++) {
            const int idx = it*256 + tid;
            const int pix = idx >> 5, j = idx & 31;
            g_rubinw32[gb + pix*32 + j] = oR[pix*36 + j];
            g_visn32  [gb + pix*32 + j] = oV[pix*36 + j];
        }
    }
}

// =========================== Kernel B (tensor-core correlation) =============
// Block = (b, 8-row tile), 256 threads, 8 warps, 1 block/SM.
// cost[dy][dx] for h in tile = ONE m16n8 GEMM over K = 8h x 64w x 64c:
//   A[m=dy][k=(w,c)] = vis[clamp(h+dy-3)][w][c]   (14 staged rows)
//   B[n=dx][k=(w,c)] = Rext[dx-3][w][c]           (shift-of-R + edge sums,
//                                                  predicated loads, no copy)
// Warp wi covers ksteps wi*32..+31 per h; 2 accumulator chains; smem reduce.
#define KB_WST 36                    // per-w stride (u32): 32 data + 4 pad
#define KB_VST 2308                  // vis row stride (64*36 + 4)
#define KB_RST 2304                  // rubin row stride (64*36)
#define KB_VIS_U32 (14*KB_VST)       // 32312
#define KB_RUB_OFF KB_VIS_U32
#define KB_ES_OFF  (KB_RUB_OFF + 8*KB_RST)          // 50744
#define KB_SRED_OFF (KB_ES_OFF + 8*7*KB_WST)        // 52760
#define KB_SMEM_BYTES ((KB_SRED_OFF + 8*KK + 8)*4)  // ~212.8 KB

__global__ void __launch_bounds__(256, 1)
kB()
{
    extern __shared__ u32 sm32[];
    u32* visS = sm32;
    u32* rubS = sm32 + KB_RUB_OFF;
    u32* esS  = sm32 + KB_ES_OFF;
    float* sred = (float*)(sm32 + KB_SRED_OFF);

    const int tile = blockIdx.x, b = blockIdx.y;
    const int h0 = tile*8;
    const int tid = threadIdx.x;
    const int wi = tid >> 5, lane = tid & 31;
    const int g = lane >> 2, tg = lane & 3;

    const u32* vbat = g_visn32   + (size_t)b*NPIX*32;
    const u32* rbat = g_rubinw32 + (size_t)b*NPIX*32;

    // ---- stage vis (14 clamped rows) + rubin (8 rows), cp.async 16B ----
    for (int idx = tid; idx < 14*64*8; idx += 256) {
        const int m = idx & 7, w = (idx>>3)&63, t = idx>>9;
        const int gr = min(max(h0 + t - 3, 0), 63);
        const u32* src = vbat + ((size_t)(gr*64 + w))*32 + m*4;
        u32 d = (u32)__cvta_generic_to_shared(&visS[t*KB_VST + w*KB_WST + m*4]);
        asm volatile("cp.async.cg.shared.global [%0], [%1], 16;"
                     :: "r"(d), "l"(src) : "memory");
    }
    for (int idx = tid; idx < 8*64*8; idx += 256) {
        const int m = idx & 7, w = (idx>>3)&63, hh = idx>>9;
        const u32* src = rbat + ((size_t)((h0 + hh)*64 + w))*32 + m*4;
        u32 d = (u32)__cvta_generic_to_shared(&rubS[hh*KB_RST + w*KB_WST + m*4]);
        asm volatile("cp.async.cg.shared.global [%0], [%1], 16;"
                     :: "r"(d), "l"(src) : "memory");
    }
    asm volatile("cp.async.commit_group;" ::: "memory");
    asm volatile("cp.async.wait_group 0;" ::: "memory");
    __syncthreads();

    // ---- edge sums: ES[hh][s+3][c] = sum of clamp-folded R rows ----
    for (int idx = tid; idx < 8*6*32; idx += 256) {
        const int cu = idx & 31;
        const int si = (idx >> 5) % 6;            // 0..5
        const int hh = idx / (6*32);
        const int s  = (si < 3) ? (si + 1) : -(si - 2);   // 1,2,3,-1,-2,-3
        float lo = 0.f, hi = 0.f;
        const int w0 = (s > 0) ? (63 - s) : 0;
        const int w1 = (s > 0) ? 63 : (-s);
        for (int w = w0; w <= w1; w++) {
            float2 f = upk(bfpair(rubS[hh*KB_RST + w*KB_WST + cu]));
            lo += f.x; hi += f.y;
        }
        esS[(hh*7 + (s+3))*KB_WST + cu] = pack_bf2(lo, hi);
    }
    __syncthreads();

    // ---- mainloop: 8 h x 32 ksteps per warp, 2 HMMA chains ----
    float ca[4] = {0,0,0,0}, cb[4] = {0,0,0,0};
    const int s = g - 3;

    for (int hh = 0; hh < 8; hh++) {
        const u32* Rrow = rubS + hh*KB_RST;
        const u32* ESh  = esS + hh*7*KB_WST;
        const int vr = min(hh + g, 13);
        const u32* Vrow = visS + vr*KB_VST;
#pragma unroll
        for (int j = 0; j < 32; j++) {
            const int ks = wi*32 + j;
            const int w = ks >> 2, cu = (ks & 3) * 8;
            u32 a[4];
            a[0] = Vrow[w*KB_WST + cu + tg];
            a[2] = Vrow[w*KB_WST + cu + tg + 4];
            a[1] = 0u; a[3] = 0u;
            const int ridx = w - s;
            u32 b0 = 0u, b1 = 0u;
            if (g < 7 && ridx >= 0 && ridx <= 63) {
                const bool edge = (s > 0 && w == 63) || (s < 0 && w == 0);
                const u32* bp = edge ? (ESh + (s+3)*KB_WST) : (Rrow + ridx*KB_WST);
                b0 = bp[cu + tg];
                b1 = bp[cu + tg + 4];
            }
            if (j & 1) mma16816(cb, a, b0, b1);
            else       mma16816(ca, a, b0, b1);
        }
    }
#pragma unroll
    for (int j = 0; j < 4; j++) ca[j] += cb[j];

    // ---- reduce: thread (g,tg) holds cost[dy=g][dx=2tg, 2tg+1] ----
    {
        float* sw = sred + wi*KK;
        if (g < 7) {
            sw[g*7 + 2*tg] = ca[0];
            if (tg < 3) sw[g*7 + 2*tg + 1] = ca[1];
        }
    }
    __syncthreads();
    if (tid < KK) {
        float v = 0.f;
        for (int wj = 0; wj < 8; wj++) v += sred[wj*KK + tid];
        g_costpart[(b*8 + tile)*KK + tid] = v;
    }
}

// =========================== Kernel C (unchanged) ===========================
__device__ __forceinline__ float gelu_exact(float x) {
    return 0.5f * x * (1.f + erff(x * 0.70710678118654752440f));
}

__global__ void __launch_bounds__(128)
kC(const float* __restrict__ p2s, const int* __restrict__ band_idx,
   const float* __restrict__ log_temp, const float* __restrict__ band_emb,
   const float* __restrict__ w1, const float* __restrict__ b1,
   const float* __restrict__ w2, const float* __restrict__ b2,
   const float* __restrict__ w3, const float* __restrict__ b3,
   float* __restrict__ out, int stride)
{
    const int b = blockIdx.x, tid = threadIdx.x;
    __shared__ float sfeat[212];
    __shared__ float scost[KK];
    __shared__ float sh1[128], sh2[128], sout3[3];
    __shared__ float sS, scdx, scdy, sconf;

    if (tid == 0) {
        float s = 0.f;
        for (int h = 0; h < NH; h++) s += g_Spart[b*NH + h];
        sS = s;
    }
    if (tid < KK) {
        float c = 0.f;
        for (int t = 0; t < 8; t++) c += g_costpart[(b*8 + t)*KK + tid];
        scost[tid] = c;
    }
    if (tid < 64) {
        float pr = 0.f, pv = 0.f;
        for (int h = 0; h < NH; h++) {
            pr += g_poolr[(b*NH + h)*NC + tid];
            pv += g_poolv[(b*NH + h)*NC + tid];
        }
        sfeat[tid] = pr; sfeat[64 + tid] = pv; sfeat[128 + tid] = pr - pv;
    }
    __syncthreads();

    if (tid == 0) {
        const float temp  = fmaxf(expf(log_temp[0]), 1e-3f);
        const float scale = 1.f / ((sS + 1e-8f) * 8.f * temp);
        float l[KK], mx = -1e30f;
        for (int k = 0; k < KK; k++) { l[k] = scost[k] * scale; mx = fmaxf(mx, l[k]); }
        float sum = 0.f;
        for (int k = 0; k < KK; k++) { float p = expf(l[k] - mx); l[k] = p; sum += p; }
        const float inv = 1.f / sum;
        float cdx = 0.f, cdy = 0.f, cf = 0.f;
        for (int k = 0; k < KK; k++) {
            float p = l[k] * inv;
            cf  = fmaxf(cf, p);
            cdx += p * (float)((k % 7) - 3);
            cdy += p * (float)((k / 7) - 3);
        }
        scdx = cdx; scdy = cdy; sconf = cf;
        sfeat[192] = cdx; sfeat[193] = cdy;
    }
    if (tid < 16) sfeat[194 + tid] = band_emb[band_idx[b]*16 + tid];
    __syncthreads();

    float a = b1[tid];
    for (int f = 0; f < 210; f++) a = fmaf(sfeat[f], w1[f*128 + tid], a);
    sh1[tid] = gelu_exact(a);
    __syncthreads();

    a = b2[tid];
    for (int f = 0; f < 128; f++) a = fmaf(sh1[f], w2[f*128 + tid], a);
    sh2[tid] = gelu_exact(a);
    __syncthreads();

    if (tid < 3) {
        float a3 = b3[tid];
        for (int f = 0; f < 128; f++) a3 = fmaf(sh2[f], w3[f*3 + tid], a3);
        sout3[tid] = a3;
    }
    __syncthreads();

    if (tid == 0) {
        const float dx = scdx + sout3[0];
        const float dy = scdy + sout3[1];
        const float ls = fminf(fmaxf(sout3[2], -6.f), 3.f);
        const float s0 = p2s[b*4 + 0]*dx + p2s[b*4 + 1]*dy;
        const float s1 = p2s[b*4 + 2]*dx + p2s[b*4 + 3]*dy;
        float* o = out + (size_t)b * stride;
        if (stride > 0) o[0] = dx;
        if (stride > 1) o[1] = dy;
        if (stride > 2) o[2] = s0;
        if (stride > 3) o[3] = s1;
        if (stride > 4) o[4] = ls;
        if (stride > 5) o[5] = sconf;
        for (int j = 6; j < stride; j++) o[j] = 0.f;
    }
}

// =========================== launch =========================================
extern "C" void kernel_launch(void* const* d_in, const int* in_sizes, int n_in,
                              void* d_out, int out_size)
{
    const float* rubin = (const float*)d_in[0];
    const float* vis   = (const float*)d_in[1];
    const float* p2s   = (const float*)d_in[2];
    const int*   bidx  = (const int*)  d_in[3];
    const float* wr    = (const float*)d_in[4];
    const float* wv    = (const float*)d_in[5];
    const float* lt    = (const float*)d_in[6];
    const float* bemb  = (const float*)d_in[7];
    const float* w1    = (const float*)d_in[8];
    const float* b1    = (const float*)d_in[9];
    const float* w2    = (const float*)d_in[10];
    const float* b2    = (const float*)d_in[11];
    const float* w3    = (const float*)d_in[12];
    const float* b3    = (const float*)d_in[13];
    float* out = (float*)d_out;
    const int stride = out_size / NB;

    double Sy = 0.0;
    for (int i = 0; i < 64; i++) {
        double y = -1.0 + 2.0 * (double)i / 63.0;
        Sy += exp(-2.0 * y * y);
    }
    const float inv_gsum = (float)(1.0 / (Sy * Sy));

    cudaFuncSetAttribute(kA, cudaFuncAttributeMaxDynamicSharedMemorySize, KA_SMEM_BYTES);
    cudaFuncSetAttribute(kB, cudaFuncAttributeMaxDynamicSharedMemorySize, KB_SMEM_BYTES);

    kA<<<dim3(NH/2, NB), 256, KA_SMEM_BYTES>>>(rubin, vis, wr, wv, inv_gsum);
    kB<<<dim3(8, NB), 256, KB_SMEM_BYTES>>>();
    kC<<<NB, 128>>>(p2s, bidx, lt, bemb, w1, b1, w2, b2, w3, b3, out, stride);
}